// round 10
// baseline (speedup 1.0000x reference)
#include <cuda_runtime.h>
#include <cuda_bf16.h>
#include <cstdint>
#include <math.h>

#define TOK   8192
#define EMBD  1024
#define SEQ   2048
#define NHEAD 16
#define HDIM  64

// ---------------- scratch (allocation-free rule: device globals) ----------
__device__ float g_qkv[(size_t)TOK * 3 * EMBD];
__device__ __nv_bfloat16 g_xh[(size_t)TOK * EMBD];
__device__ __nv_bfloat16 g_xl[(size_t)TOK * EMBD];
__device__ __nv_bfloat16 g_ch[(size_t)TOK * EMBD];
__device__ __nv_bfloat16 g_cl[(size_t)TOK * EMBD];
__device__ __nv_bfloat16 g_wqh[(size_t)3 * EMBD * EMBD];
__device__ __nv_bfloat16 g_wql[(size_t)3 * EMBD * EMBD];
__device__ __nv_bfloat16 g_woh[(size_t)EMBD * EMBD];
__device__ __nv_bfloat16 g_wol[(size_t)EMBD * EMBD];
// attention operands (split bf16, prepped once)
__device__ __nv_bfloat16 g_qsh[(size_t)TOK * EMBD];
__device__ __nv_bfloat16 g_qsl[(size_t)TOK * EMBD];
__device__ __nv_bfloat16 g_ksh[(size_t)TOK * EMBD];
__device__ __nv_bfloat16 g_ksl[(size_t)TOK * EMBD];
__device__ __nv_bfloat16 g_vth[(size_t)TOK * EMBD];
__device__ __nv_bfloat16 g_vtl[(size_t)TOK * EMBD];

// ---------------- helpers ---------------------------------------------
__device__ __forceinline__ uint32_t smem_u32(const void* p) {
    uint32_t a;
    asm("{ .reg .u64 t; cvta.to.shared.u64 t, %1; cvt.u32.u64 %0, t; }" : "=r"(a) : "l"(p));
    return a;
}

#define LDSM4(r, a) \
    asm volatile("ldmatrix.sync.aligned.m8n8.x4.shared.b16 {%0,%1,%2,%3}, [%4];" \
        : "=r"((r)[0]), "=r"((r)[1]), "=r"((r)[2]), "=r"((r)[3]) : "r"(a))

#define MMA_BF16(c, a, b0, b1) \
    asm volatile("mma.sync.aligned.m16n8k16.row.col.f32.bf16.bf16.f32 " \
        "{%0,%1,%2,%3},{%4,%5,%6,%7},{%8,%9},{%0,%1,%2,%3};" \
        : "+f"((c)[0]), "+f"((c)[1]), "+f"((c)[2]), "+f"((c)[3]) \
        : "r"((a)[0]), "r"((a)[1]), "r"((a)[2]), "r"((a)[3]), "r"(b0), "r"(b1))

#define CP_ASYNC16(so, gp) \
    asm volatile("cp.async.cg.shared.global [%0], [%1], 16;" :: "r"(so), "l"(gp) : "memory")
#define CP_COMMIT() asm volatile("cp.async.commit_group;" ::: "memory")
#define CP_WAIT0()  asm volatile("cp.async.wait_group 0;" ::: "memory")
#define CP_WAIT1()  asm volatile("cp.async.wait_group 1;" ::: "memory")

// fast exp2 on fma pipe (arg <= 0, clamped), rel err ~2e-5
__device__ __forceinline__ float exp2f_fast(float t) {
    t = fmaxf(t, -100.0f);
    float fi = floorf(t);
    float f  = t - fi;
    float p  = 1.33335581e-3f;
    p = fmaf(p, f, 9.61812910e-3f);
    p = fmaf(p, f, 5.55041087e-2f);
    p = fmaf(p, f, 2.40226507e-1f);
    p = fmaf(p, f, 6.93147182e-1f);
    p = fmaf(p, f, 1.0f);
    return __int_as_float(((int)fi + 127) << 23) * p;
}

__device__ __forceinline__ void split2(float x, float y, uint32_t& hi, uint32_t& lo) {
    __nv_bfloat162 h2 = __floats2bfloat162_rn(x, y);
    float2 hf = __bfloat1622float2(h2);
    __nv_bfloat162 l2 = __floats2bfloat162_rn(x - hf.x, y - hf.y);
    hi = *reinterpret_cast<uint32_t*>(&h2);
    lo = *reinterpret_cast<uint32_t*>(&l2);
}

// ---------------------------------------------------------------------------
// mma.sync split-bf16 GEMM, block tile 256x128 (M x N), warp tile 64x64,
// 3-stage cp.async ring. C[M,N] = (Ah+Al)@(Bh+Bl)^T + bias (HH+HL+LH terms).
// ---------------------------------------------------------------------------
#define LDB     80
#define A_TILE  (256 * LDB)                 // 20480 B
#define B_TILE  (128 * LDB)                 // 10240 B
#define GSTAGE  (2 * A_TILE + 2 * B_TILE)   // 61440 B
#define GSMEM   (3 * GSTAGE)                // 184320 B

__global__ __launch_bounds__(256, 1) void gemm_mma(
    const __nv_bfloat16* __restrict__ Ah, const __nv_bfloat16* __restrict__ Al,
    const __nv_bfloat16* __restrict__ Bh, const __nv_bfloat16* __restrict__ Bl,
    const float* __restrict__ bias, float* __restrict__ C, int N)
{
    extern __shared__ char smem[];
    const uint32_t sbase = smem_u32(smem);
    const int tid = threadIdx.x;
    const int wid = tid >> 5;
    const int l   = tid & 31;
    const int m0  = blockIdx.y * 256;
    const int n0  = blockIdx.x * 128;
    const int wm  = (wid >> 1) * 64;       // warp m offset 0..192
    const int wn  = (wid & 1) * 64;        // warp n offset 0/64

    const int frow = (l & 7) + ((l >> 3) & 1) * 8;
    const int fkb  = (l >> 4) * 16;

    float acc[4][8][4];
    #pragma unroll
    for (int a = 0; a < 4; ++a)
        #pragma unroll
        for (int b = 0; b < 8; ++b)
            #pragma unroll
            for (int c = 0; c < 4; ++c) acc[a][b][c] = 0.f;

    auto load_stage = [&](int ks) {
        const uint32_t sb = sbase + (ks % 3) * GSTAGE;
        const int kc = ks * 32;
        // A tiles: 256 rows x 2 (hi/lo), 4 chunks of 16B per row
        #pragma unroll
        for (int t = 0; t < 4; ++t) {
            const int chunk = t * 256 + tid;
            const int row = chunk >> 2, seg = chunk & 3;
            const size_t g = (size_t)(m0 + row) * 1024 + kc + seg * 8;
            const uint32_t o = sb + row * LDB + seg * 16;
            CP_ASYNC16(o,          Ah + g);
            CP_ASYNC16(o + A_TILE, Al + g);
        }
        // B tiles: 128 rows x 2
        #pragma unroll
        for (int t = 0; t < 2; ++t) {
            const int chunk = t * 256 + tid;
            const int row = chunk >> 2, seg = chunk & 3;
            const size_t g = (size_t)(n0 + row) * 1024 + kc + seg * 8;
            const uint32_t o = sb + 2 * A_TILE + row * LDB + seg * 16;
            CP_ASYNC16(o,          Bh + g);
            CP_ASYNC16(o + B_TILE, Bl + g);
        }
    };

    load_stage(0); CP_COMMIT();
    load_stage(1); CP_COMMIT();

    for (int ks = 0; ks < 32; ++ks) {
        if (ks < 31) CP_WAIT1(); else CP_WAIT0();
        __syncthreads();
        if (ks + 2 < 32) { load_stage(ks + 2); CP_COMMIT(); }

        const uint32_t sb = sbase + (ks % 3) * GSTAGE;
        #pragma unroll
        for (int kk = 0; kk < 2; ++kk) {
            const uint32_t kbo = kk * 32 + fkb;
            uint32_t ah[4][4], al_[4][4], bh[4][4], bl_[4][4];
            #pragma unroll
            for (int mt = 0; mt < 4; ++mt) {
                const uint32_t addr = sb + (wm + mt * 16 + frow) * LDB + kbo;
                LDSM4(ah[mt], addr);
                LDSM4(al_[mt], addr + A_TILE);
            }
            #pragma unroll
            for (int p = 0; p < 4; ++p) {
                const uint32_t addr = sb + 2 * A_TILE + (wn + p * 16 + frow) * LDB + kbo;
                LDSM4(bh[p], addr);
                LDSM4(bl_[p], addr + B_TILE);
            }
            #pragma unroll
            for (int mt = 0; mt < 4; ++mt)
                #pragma unroll
                for (int nt = 0; nt < 8; ++nt) {
                    const int p = nt >> 1, o = nt & 1;
                    MMA_BF16(acc[mt][nt], ah[mt],  bh[p][0 + o],  bh[p][2 + o]);
                    MMA_BF16(acc[mt][nt], ah[mt],  bl_[p][0 + o], bl_[p][2 + o]);
                    MMA_BF16(acc[mt][nt], al_[mt], bh[p][0 + o],  bh[p][2 + o]);
                }
        }
    }

    const int er = l >> 2, ec = (l & 3) * 2;
    #pragma unroll
    for (int mt = 0; mt < 4; ++mt) {
        #pragma unroll
        for (int nt = 0; nt < 8; ++nt) {
            const int m = m0 + wm + mt * 16 + er;
            const int n = n0 + wn + nt * 8 + ec;
            const float b0 = __ldg(bias + n), b1 = __ldg(bias + n + 1);
            float2 v0 = { acc[mt][nt][0] + b0, acc[mt][nt][1] + b1 };
            float2 v1 = { acc[mt][nt][2] + b0, acc[mt][nt][3] + b1 };
            *(float2*)(C + (size_t)m * N + n)       = v0;
            *(float2*)(C + (size_t)(m + 8) * N + n) = v1;
        }
    }
}

// ---------------------------------------------------------------------------
// HMMA flash attention (pre-split operands; heavy q-tiles scheduled first)
// ---------------------------------------------------------------------------
#define AT    8192
#define ASTG  (4 * AT)
#define ASMEM (2 * AT + 2 * ASTG)

__global__ __launch_bounds__(128) void attn_mma(
    const __nv_bfloat16* __restrict__ Qh, const __nv_bfloat16* __restrict__ Ql,
    const __nv_bfloat16* __restrict__ Kh, const __nv_bfloat16* __restrict__ Kl,
    const __nv_bfloat16* __restrict__ Vth, const __nv_bfloat16* __restrict__ Vtl,
    __nv_bfloat16* __restrict__ Ch, __nv_bfloat16* __restrict__ Cl)
{
    extern __shared__ char smem[];
    const uint32_t sQ = smem_u32(smem);

    const int qt  = gridDim.x - 1 - blockIdx.x;   // heavy tiles first
    const int h   = blockIdx.y;
    const int b   = blockIdx.z;
    const int tid = threadIdx.x;
    const int w   = tid >> 5;
    const int l   = tid & 31;
    const int q0  = qt * 64;

    const int lr  = tid >> 1;
    const int lc  = tid & 1;

    const int frow = (l & 7) + ((l >> 3) & 1) * 8;
    const int fch  = l >> 4;

    {
        const __nv_bfloat16* qs = Qh + (size_t)(b * SEQ + q0 + lr) * EMBD + h * HDIM;
        const __nv_bfloat16* qsl2 = Ql + (size_t)(b * SEQ + q0 + lr) * EMBD + h * HDIM;
        #pragma unroll
        for (int i = 0; i < 4; ++i) {
            const int c = lc * 4 + i;
            const uint32_t o = lr * 128 + ((c ^ (lr & 7)) << 4);
            CP_ASYNC16(sQ + o,      qs + c * 8);
            CP_ASYNC16(sQ + AT + o, qsl2 + c * 8);
        }
    }
    auto load_stage = [&](int kt, int buf) {
        const uint32_t sb = sQ + 2 * AT + buf * ASTG;
        const __nv_bfloat16* ks = Kh + (size_t)(b * SEQ + kt * 64 + lr) * EMBD + h * HDIM;
        const __nv_bfloat16* kls = Kl + (size_t)(b * SEQ + kt * 64 + lr) * EMBD + h * HDIM;
        const __nv_bfloat16* vs = Vth + (size_t)((b * NHEAD + h) * HDIM + lr) * SEQ + kt * 64;
        const __nv_bfloat16* vls = Vtl + (size_t)((b * NHEAD + h) * HDIM + lr) * SEQ + kt * 64;
        #pragma unroll
        for (int i = 0; i < 4; ++i) {
            const int c = lc * 4 + i;
            const uint32_t o = lr * 128 + ((c ^ (lr & 7)) << 4);
            CP_ASYNC16(sb + o,          ks + c * 8);
            CP_ASYNC16(sb + AT + o,     kls + c * 8);
            CP_ASYNC16(sb + 2 * AT + o, vs + c * 8);
            CP_ASYNC16(sb + 3 * AT + o, vls + c * 8);
        }
    };
    load_stage(0, 0);
    CP_COMMIT();

    float o_[8][4];
    #pragma unroll
    for (int nt = 0; nt < 8; ++nt)
        #pragma unroll
        for (int c = 0; c < 4; ++c) o_[nt][c] = 0.f;
    float mA = -1e30f, mB = -1e30f, lA = 0.f, lB = 0.f;

    const int rA = w * 16 + (l >> 2);
    const int cBase = (l & 3) * 2;

    for (int kt = 0; kt <= qt; ++kt) {
        const int buf = kt & 1;
        CP_WAIT0();
        __syncthreads();
        if (kt < qt) { load_stage(kt + 1, buf ^ 1); CP_COMMIT(); }

        const uint32_t sb = sQ + 2 * AT + buf * ASTG;

        float s[8][4];
        #pragma unroll
        for (int nt = 0; nt < 8; ++nt)
            #pragma unroll
            for (int c = 0; c < 4; ++c) s[nt][c] = 0.f;

        #pragma unroll
        for (int kk = 0; kk < 4; ++kk) {
            const int cI = kk * 2 + fch;
            uint32_t qh[4], ql[4], kh[4][4], kl[4][4];
            {
                const int qr = w * 16 + frow;
                const uint32_t qa = sQ + qr * 128 + ((cI ^ (qr & 7)) << 4);
                LDSM4(qh, qa);
                LDSM4(ql, qa + AT);
            }
            #pragma unroll
            for (int p = 0; p < 4; ++p) {
                const int kr = p * 16 + frow;
                const uint32_t ka = sb + kr * 128 + ((cI ^ (kr & 7)) << 4);
                LDSM4(kh[p], ka);
                LDSM4(kl[p], ka + AT);
            }
            #pragma unroll
            for (int nt = 0; nt < 8; ++nt) {
                const int p = nt >> 1, o = nt & 1;
                MMA_BF16(s[nt], qh, kh[p][0 + o], kh[p][2 + o]);
                MMA_BF16(s[nt], qh, kl[p][0 + o], kl[p][2 + o]);
                MMA_BF16(s[nt], ql, kh[p][0 + o], kh[p][2 + o]);
            }
        }

        if (kt == qt) {
            #pragma unroll
            for (int nt = 0; nt < 8; ++nt) {
                const int c0 = nt * 8 + cBase;
                if (c0 > rA)         s[nt][0] = -1e30f;
                if (c0 + 1 > rA)     s[nt][1] = -1e30f;
                if (c0 > rA + 8)     s[nt][2] = -1e30f;
                if (c0 + 1 > rA + 8) s[nt][3] = -1e30f;
            }
        }

        float mlA = -1e30f, mlB = -1e30f;
        #pragma unroll
        for (int nt = 0; nt < 8; ++nt) {
            mlA = fmaxf(mlA, fmaxf(s[nt][0], s[nt][1]));
            mlB = fmaxf(mlB, fmaxf(s[nt][2], s[nt][3]));
        }
        mlA = fmaxf(mlA, __shfl_xor_sync(0xffffffffu, mlA, 1));
        mlA = fmaxf(mlA, __shfl_xor_sync(0xffffffffu, mlA, 2));
        mlB = fmaxf(mlB, __shfl_xor_sync(0xffffffffu, mlB, 1));
        mlB = fmaxf(mlB, __shfl_xor_sync(0xffffffffu, mlB, 2));
        const float mAn = fmaxf(mA, mlA);
        const float mBn = fmaxf(mB, mlB);
        const float aAl = exp2f_fast(mA - mAn);
        const float aBl = exp2f_fast(mB - mBn);
        mA = mAn; mB = mBn;

        float sumA = 0.f, sumB = 0.f;
        #pragma unroll
        for (int nt = 0; nt < 8; ++nt) {
            s[nt][0] = exp2f_fast(s[nt][0] - mAn);
            s[nt][1] = exp2f_fast(s[nt][1] - mAn);
            s[nt][2] = exp2f_fast(s[nt][2] - mBn);
            s[nt][3] = exp2f_fast(s[nt][3] - mBn);
            sumA += s[nt][0] + s[nt][1];
            sumB += s[nt][2] + s[nt][3];
        }
        sumA += __shfl_xor_sync(0xffffffffu, sumA, 1);
        sumA += __shfl_xor_sync(0xffffffffu, sumA, 2);
        sumB += __shfl_xor_sync(0xffffffffu, sumB, 1);
        sumB += __shfl_xor_sync(0xffffffffu, sumB, 2);
        lA = lA * aAl + sumA;
        lB = lB * aBl + sumB;

        #pragma unroll
        for (int nt = 0; nt < 8; ++nt) {
            o_[nt][0] *= aAl; o_[nt][1] *= aAl;
            o_[nt][2] *= aBl; o_[nt][3] *= aBl;
        }

        #pragma unroll
        for (int kp = 0; kp < 4; ++kp) {
            uint32_t pha[4], pla[4];
            split2(s[2 * kp][0],     s[2 * kp][1],     pha[0], pla[0]);
            split2(s[2 * kp][2],     s[2 * kp][3],     pha[1], pla[1]);
            split2(s[2 * kp + 1][0], s[2 * kp + 1][1], pha[2], pla[2]);
            split2(s[2 * kp + 1][2], s[2 * kp + 1][3], pha[3], pla[3]);

            const int cI = kp * 2 + fch;
            uint32_t vh[4][4], vl[4][4];
            #pragma unroll
            for (int p = 0; p < 4; ++p) {
                const int vr = p * 16 + frow;
                const uint32_t va = sb + 2 * AT + vr * 128 + ((cI ^ (vr & 7)) << 4);
                LDSM4(vh[p], va);
                LDSM4(vl[p], va + AT);
            }
            #pragma unroll
            for (int nt = 0; nt < 8; ++nt) {
                const int p = nt >> 1, o = nt & 1;
                MMA_BF16(o_[nt], pha, vh[p][0 + o], vh[p][2 + o]);
                MMA_BF16(o_[nt], pha, vl[p][0 + o], vl[p][2 + o]);
                MMA_BF16(o_[nt], pla, vh[p][0 + o], vh[p][2 + o]);
            }
        }
    }

    const float iA = 1.0f / lA, iB = 1.0f / lB;
    const size_t row0 = (size_t)(b * SEQ + q0 + rA);
    #pragma unroll
    for (int nt = 0; nt < 8; ++nt) {
        const int d = h * HDIM + nt * 8 + cBase;
        uint32_t h0, l0, h1, l1;
        split2(o_[nt][0] * iA, o_[nt][1] * iA, h0, l0);
        split2(o_[nt][2] * iB, o_[nt][3] * iB, h1, l1);
        *(uint32_t*)(Ch + row0 * EMBD + d)       = h0;
        *(uint32_t*)(Cl + row0 * EMBD + d)       = l0;
        *(uint32_t*)(Ch + (row0 + 8) * EMBD + d) = h1;
        *(uint32_t*)(Cl + (row0 + 8) * EMBD + d) = l1;
    }
}

// ---------------------------------------------------------------------------
// prep kernels (unchanged)
// ---------------------------------------------------------------------------
static __device__ __forceinline__ unsigned pack2(float a, float b) {
    __nv_bfloat162 t = __floats2bfloat162_rn(a, b);
    return *reinterpret_cast<unsigned*>(&t);
}
__global__ __launch_bounds__(256) void split_pair(
    const float4* __restrict__ src, uint2* __restrict__ h, uint2* __restrict__ l, int n4)
{
    const int i = blockIdx.x * 256 + threadIdx.x;
    if (i >= n4) return;
    const float4 v = src[i];
    const float hx = __bfloat162float(__float2bfloat16(v.x));
    const float hy = __bfloat162float(__float2bfloat16(v.y));
    const float hz = __bfloat162float(__float2bfloat16(v.z));
    const float hw = __bfloat162float(__float2bfloat16(v.w));
    h[i] = make_uint2(pack2(v.x, v.y), pack2(v.z, v.w));
    l[i] = make_uint2(pack2(v.x - hx, v.y - hy), pack2(v.z - hz, v.w - hw));
}

__global__ __launch_bounds__(256) void qk_split(
    const float* __restrict__ qkv,
    uint2* __restrict__ qh, uint2* __restrict__ ql,
    uint2* __restrict__ kh, uint2* __restrict__ kl)
{
    const float QSC = 0.1803368801111244f;
    const int i = blockIdx.x * 256 + threadIdx.x;
    const int tok = i >> 8, c4 = (i & 255);
    {
        const float4 v = *(const float4*)(qkv + (size_t)tok * 3072 + c4 * 4);
        const float x = v.x * QSC, y = v.y * QSC, z = v.z * QSC, w = v.w * QSC;
        const float hx = __bfloat162float(__float2bfloat16(x));
        const float hy = __bfloat162float(__float2bfloat16(y));
        const float hz = __bfloat162float(__float2bfloat16(z));
        const float hw = __bfloat162float(__float2bfloat16(w));
        qh[(size_t)tok * 256 + c4] = make_uint2(pack2(x, y), pack2(z, w));
        ql[(size_t)tok * 256 + c4] = make_uint2(pack2(x - hx, y - hy), pack2(z - hz, w - hw));
    }
    {
        const float4 v = *(const float4*)(qkv + (size_t)tok * 3072 + 1024 + c4 * 4);
        const float hx = __bfloat162float(__float2bfloat16(v.x));
        const float hy = __bfloat162float(__float2bfloat16(v.y));
        const float hz = __bfloat162float(__float2bfloat16(v.z));
        const float hw = __bfloat162float(__float2bfloat16(v.w));
        kh[(size_t)tok * 256 + c4] = make_uint2(pack2(v.x, v.y), pack2(v.z, v.w));
        kl[(size_t)tok * 256 + c4] = make_uint2(pack2(v.x - hx, v.y - hy), pack2(v.z - hz, v.w - hw));
    }
}

__global__ void vt_split(const float* __restrict__ qkv,
                         __nv_bfloat16* __restrict__ Th,
                         __nv_bfloat16* __restrict__ Tl)
{
    __shared__ float t[32][33];
    const int t0 = blockIdx.x * 32;
    const int d0 = blockIdx.y * 32;
    const int bh = blockIdx.z;
    const int b  = bh >> 4, h = bh & 15;
    const int x = threadIdx.x, y = threadIdx.y;
    #pragma unroll
    for (int i = 0; i < 32; i += 8)
        t[y + i][x] = qkv[(size_t)(b * SEQ + t0 + y + i) * 3072 + 2048 + h * HDIM + d0 + x];
    __syncthreads();
    #pragma unroll
    for (int i = 0; i < 32; i += 8) {
        const float v = t[x][y + i];
        const __nv_bfloat16 hv = __float2bfloat16(v);
        const size_t o = (size_t)(bh * HDIM + d0 + y + i) * SEQ + t0 + x;
        Th[o] = hv;
        Tl[o] = __float2bfloat16(v - __bfloat162float(hv));
    }
}

__global__ void transpose_split(const float* __restrict__ W,
                                __nv_bfloat16* __restrict__ Th,
                                __nv_bfloat16* __restrict__ Tl, int K, int N)
{
    __shared__ float t[32][33];
    const int k0 = blockIdx.y * 32, n0 = blockIdx.x * 32;
    const int x = threadIdx.x, y = threadIdx.y;
    #pragma unroll
    for (int i = 0; i < 32; i += 8)
        t[y + i][x] = W[(size_t)(k0 + y + i) * N + n0 + x];
    __syncthreads();
    #pragma unroll
    for (int i = 0; i < 32; i += 8) {
        const float v = t[x][y + i];
        const __nv_bfloat16 hv = __float2bfloat16(v);
        const size_t o = (size_t)(n0 + y + i) * K + k0 + x;
        Th[o] = hv;
        Tl[o] = __float2bfloat16(v - __bfloat162float(hv));
    }
}

// ---------------------------------------------------------------------------
extern "C" void kernel_launch(void* const* d_in, const int* in_sizes, int n_in,
                              void* d_out, int out_size)
{
    const float* x     = (const float*)d_in[0];
    const float* w_qkv = (const float*)d_in[1];
    const float* b_qkv = (const float*)d_in[2];
    const float* w_out = (const float*)d_in[3];
    const float* b_out = (const float*)d_in[4];
    float* out = (float*)d_out;

    float* qkv;
    __nv_bfloat16 *xh, *xl, *ch, *cl, *wqh, *wql, *woh, *wol;
    __nv_bfloat16 *qsh, *qsl, *ksh, *ksl, *vth, *vtl;
    cudaGetSymbolAddress((void**)&qkv, g_qkv);
    cudaGetSymbolAddress((void**)&xh, g_xh);
    cudaGetSymbolAddress((void**)&xl, g_xl);
    cudaGetSymbolAddress((void**)&ch, g_ch);
    cudaGetSymbolAddress((void**)&cl, g_cl);
    cudaGetSymbolAddress((void**)&wqh, g_wqh);
    cudaGetSymbolAddress((void**)&wql, g_wql);
    cudaGetSymbolAddress((void**)&woh, g_woh);
    cudaGetSymbolAddress((void**)&wol, g_wol);
    cudaGetSymbolAddress((void**)&qsh, g_qsh);
    cudaGetSymbolAddress((void**)&qsl, g_qsl);
    cudaGetSymbolAddress((void**)&ksh, g_ksh);
    cudaGetSymbolAddress((void**)&ksl, g_ksl);
    cudaGetSymbolAddress((void**)&vth, g_vth);
    cudaGetSymbolAddress((void**)&vtl, g_vtl);

    cudaFuncSetAttribute(gemm_mma, cudaFuncAttributeMaxDynamicSharedMemorySize, GSMEM);
    cudaFuncSetAttribute(attn_mma, cudaFuncAttributeMaxDynamicSharedMemorySize, ASMEM);

    const int n4 = TOK * EMBD / 4;

    split_pair<<<n4 / 256, 256>>>((const float4*)x, (uint2*)xh, (uint2*)xl, n4);
    transpose_split<<<dim3(3 * EMBD / 32, EMBD / 32), dim3(32, 8)>>>(w_qkv, wqh, wql, EMBD, 3 * EMBD);
    transpose_split<<<dim3(EMBD / 32, EMBD / 32), dim3(32, 8)>>>(w_out, woh, wol, EMBD, EMBD);

    // 1) qkv = x @ w_qkv + b_qkv   (256x128 tiles)
    gemm_mma<<<dim3(3 * EMBD / 128, TOK / 256), 256, GSMEM>>>(xh, xl, wqh, wql, b_qkv, qkv, 3 * EMBD);

    // 2) prep attention operands
    qk_split<<<TOK, 256>>>(qkv, (uint2*)qsh, (uint2*)qsl, (uint2*)ksh, (uint2*)ksl);
    vt_split<<<dim3(SEQ / 32, HDIM / 32, 4 * NHEAD), dim3(32, 8)>>>(qkv, vth, vtl);

    // 3) causal flash attention
    attn_mma<<<dim3(SEQ / 64, NHEAD, 4), 128, ASMEM>>>(qsh, qsl, ksh, ksl, vth, vtl, ch, cl);

    // 4) out = ctx @ w_out + b_out
    gemm_mma<<<dim3(EMBD / 128, TOK / 256), 256, GSMEM>>>(ch, cl, woh, wol, b_out, out, EMBD);
}

// round 12
// speedup vs baseline: 1.3218x; 1.3218x over previous
#include <cuda_runtime.h>
#include <cuda_bf16.h>
#include <cuda_fp16.h>
#include <cstdint>
#include <math.h>

#define TOK   8192
#define EMBD  1024
#define SEQ   2048
#define NHEAD 16
#define HDIM  64

// ---------------- scratch (allocation-free rule: device globals) ----------
__device__ float g_qkv[(size_t)TOK * 3 * EMBD];
__device__ __nv_bfloat16 g_xh[(size_t)TOK * EMBD];
__device__ __nv_bfloat16 g_xl[(size_t)TOK * EMBD];
__device__ __nv_bfloat16 g_ch[(size_t)TOK * EMBD];
__device__ __nv_bfloat16 g_cl[(size_t)TOK * EMBD];
__device__ __nv_bfloat16 g_wqh[(size_t)3 * EMBD * EMBD];
__device__ __nv_bfloat16 g_wql[(size_t)3 * EMBD * EMBD];
__device__ __nv_bfloat16 g_woh[(size_t)EMBD * EMBD];
__device__ __nv_bfloat16 g_wol[(size_t)EMBD * EMBD];
// attention operands (fp16, prepped once)
__device__ __half g_qs[(size_t)TOK * EMBD];   // scaled Q  [tok][h*64+d]
__device__ __half g_ks[(size_t)TOK * EMBD];   // K         [tok][h*64+d]
__device__ __half g_vt[(size_t)TOK * EMBD];   // V^T       [b,h,d][t]

// ---------------- helpers ---------------------------------------------
__device__ __forceinline__ uint32_t smem_u32(const void* p) {
    uint32_t a;
    asm("{ .reg .u64 t; cvta.to.shared.u64 t, %1; cvt.u32.u64 %0, t; }" : "=r"(a) : "l"(p));
    return a;
}

#define LDSM4(r, a) \
    asm volatile("ldmatrix.sync.aligned.m8n8.x4.shared.b16 {%0,%1,%2,%3}, [%4];" \
        : "=r"((r)[0]), "=r"((r)[1]), "=r"((r)[2]), "=r"((r)[3]) : "r"(a))

#define MMA_BF16(c, a, b0, b1) \
    asm volatile("mma.sync.aligned.m16n8k16.row.col.f32.bf16.bf16.f32 " \
        "{%0,%1,%2,%3},{%4,%5,%6,%7},{%8,%9},{%0,%1,%2,%3};" \
        : "+f"((c)[0]), "+f"((c)[1]), "+f"((c)[2]), "+f"((c)[3]) \
        : "r"((a)[0]), "r"((a)[1]), "r"((a)[2]), "r"((a)[3]), "r"(b0), "r"(b1))

#define MMA_FP16(c, a, b0, b1) \
    asm volatile("mma.sync.aligned.m16n8k16.row.col.f32.f16.f16.f32 " \
        "{%0,%1,%2,%3},{%4,%5,%6,%7},{%8,%9},{%0,%1,%2,%3};" \
        : "+f"((c)[0]), "+f"((c)[1]), "+f"((c)[2]), "+f"((c)[3]) \
        : "r"((a)[0]), "r"((a)[1]), "r"((a)[2]), "r"((a)[3]), "r"(b0), "r"(b1))

#define CP_ASYNC16(so, gp) \
    asm volatile("cp.async.cg.shared.global [%0], [%1], 16;" :: "r"(so), "l"(gp) : "memory")
#define CP_COMMIT() asm volatile("cp.async.commit_group;" ::: "memory")
#define CP_WAIT0()  asm volatile("cp.async.wait_group 0;" ::: "memory")

// fast exp2 on fma pipe (arg <= 0, clamped), rel err ~2e-5
__device__ __forceinline__ float exp2f_fast(float t) {
    t = fmaxf(t, -100.0f);
    float fi = floorf(t);
    float f  = t - fi;
    float p  = 1.33335581e-3f;
    p = fmaf(p, f, 9.61812910e-3f);
    p = fmaf(p, f, 5.55041087e-2f);
    p = fmaf(p, f, 2.40226507e-1f);
    p = fmaf(p, f, 6.93147182e-1f);
    p = fmaf(p, f, 1.0f);
    return __int_as_float(((int)fi + 127) << 23) * p;
}

__device__ __forceinline__ void split2(float x, float y, uint32_t& hi, uint32_t& lo) {
    __nv_bfloat162 h2 = __floats2bfloat162_rn(x, y);
    float2 hf = __bfloat1622float2(h2);
    __nv_bfloat162 l2 = __floats2bfloat162_rn(x - hf.x, y - hf.y);
    hi = *reinterpret_cast<uint32_t*>(&h2);
    lo = *reinterpret_cast<uint32_t*>(&l2);
}

__device__ __forceinline__ uint32_t packh2(float x, float y) {
    __half2 t = __floats2half2_rn(x, y);
    return *reinterpret_cast<uint32_t*>(&t);
}

// ---------------------------------------------------------------------------
// mma.sync split-bf16 GEMM (R9 config: 128x128, 2-stage, 2 blocks/SM) — proven
// ---------------------------------------------------------------------------
#define LDB    80
#define TILEB  (128 * LDB)
#define GSTAGE (4 * TILEB)
#define GSMEM  (2 * GSTAGE)

__global__ __launch_bounds__(256) void gemm_mma(
    const __nv_bfloat16* __restrict__ Ah, const __nv_bfloat16* __restrict__ Al,
    const __nv_bfloat16* __restrict__ Bh, const __nv_bfloat16* __restrict__ Bl,
    const float* __restrict__ bias, float* __restrict__ C, int N)
{
    extern __shared__ char smem[];
    const uint32_t sbase = smem_u32(smem);
    const int tid = threadIdx.x;
    const int wid = tid >> 5;
    const int l   = tid & 31;
    const int m0  = blockIdx.y * 128;
    const int n0  = blockIdx.x * 128;
    const int wm  = (wid >> 2) * 64;
    const int wn  = (wid & 3) * 32;

    const __nv_bfloat16* srcs[4] = {
        Ah + (size_t)m0 * 1024, Al + (size_t)m0 * 1024,
        Bh + (size_t)n0 * 1024, Bl + (size_t)n0 * 1024 };
    const int lrow = tid >> 2;
    const int lseg = tid & 3;

    const int frow = (l & 7) + ((l >> 3) & 1) * 8;
    const int fkb  = (l >> 4) * 16;

    float acc[4][4][4];
    #pragma unroll
    for (int a = 0; a < 4; ++a)
        #pragma unroll
        for (int b = 0; b < 4; ++b)
            #pragma unroll
            for (int c = 0; c < 4; ++c) acc[a][b][c] = 0.f;

    auto load_stage = [&](int ks, int buf) {
        const uint32_t sb = sbase + buf * GSTAGE;
        const int kc = ks * 32;
        #pragma unroll
        for (int t = 0; t < 4; ++t) {
            const __nv_bfloat16* s = srcs[t] + kc + lseg * 8;
            #pragma unroll
            for (int j = 0; j < 2; ++j) {
                const int row = lrow + j * 64;
                const uint32_t so = sb + t * TILEB + row * LDB + lseg * 16;
                CP_ASYNC16(so, s + (size_t)row * 1024);
            }
        }
    };

    load_stage(0, 0);
    CP_COMMIT();

    for (int ks = 0; ks < 32; ++ks) {
        const int buf = ks & 1;
        CP_WAIT0();
        __syncthreads();
        if (ks + 1 < 32) { load_stage(ks + 1, buf ^ 1); CP_COMMIT(); }

        const uint32_t sb = sbase + buf * GSTAGE;
        #pragma unroll
        for (int kk = 0; kk < 2; ++kk) {
            const uint32_t kbo = kk * 32 + fkb;
            uint32_t ah[4][4], al_[4][4], bh[2][4], bl_[2][4];
            #pragma unroll
            for (int mt = 0; mt < 4; ++mt) {
                const uint32_t addr = sb + (wm + mt * 16 + frow) * LDB + kbo;
                LDSM4(ah[mt], addr);
                LDSM4(al_[mt], addr + TILEB);
            }
            #pragma unroll
            for (int p = 0; p < 2; ++p) {
                const uint32_t addr = sb + 2 * TILEB + (wn + p * 16 + frow) * LDB + kbo;
                LDSM4(bh[p], addr);
                LDSM4(bl_[p], addr + TILEB);
            }
            #pragma unroll
            for (int mt = 0; mt < 4; ++mt)
                #pragma unroll
                for (int nt = 0; nt < 4; ++nt) {
                    const int p = nt >> 1, o = nt & 1;
                    MMA_BF16(acc[mt][nt], ah[mt],  bh[p][0 + o],  bh[p][2 + o]);
                    MMA_BF16(acc[mt][nt], ah[mt],  bl_[p][0 + o], bl_[p][2 + o]);
                    MMA_BF16(acc[mt][nt], al_[mt], bh[p][0 + o],  bh[p][2 + o]);
                }
        }
    }

    __syncthreads();
    const int er = l >> 2, ec = (l & 3) * 2;
    #pragma unroll
    for (int mt = 0; mt < 4; ++mt) {
        #pragma unroll
        for (int nt = 0; nt < 4; ++nt) {
            const int m = m0 + wm + mt * 16 + er;
            const int n = n0 + wn + nt * 8 + ec;
            const float b0 = __ldg(bias + n), b1 = __ldg(bias + n + 1);
            float2 v0 = { acc[mt][nt][0] + b0, acc[mt][nt][1] + b1 };
            float2 v1 = { acc[mt][nt][2] + b0, acc[mt][nt][3] + b1 };
            *(float2*)(C + (size_t)m * N + n)       = v0;
            *(float2*)(C + (size_t)(m + 8) * N + n) = v1;
        }
    }
}

// ---------------------------------------------------------------------------
// HMMA flash attention, single-pass fp16 (fp32 accumulate).
// Block: 64 q x (h,b); 4 warps x 16 q-rows. Smem: Q + 2 stages x (K,V).
// ---------------------------------------------------------------------------
#define AT    8192                  // one 64x64 fp16 tile
#define ASTG  (2 * AT)              // K,V per stage
#define ASMEM (AT + 2 * ASTG)       // 40960 B

__global__ __launch_bounds__(128) void attn_mma(
    const __half* __restrict__ Qs, const __half* __restrict__ Ks,
    const __half* __restrict__ Vt,
    __nv_bfloat16* __restrict__ Ch, __nv_bfloat16* __restrict__ Cl)
{
    extern __shared__ char smem[];
    const uint32_t sQ = smem_u32(smem);

    const int qt  = gridDim.x - 1 - blockIdx.x;   // heavy tiles first
    const int h   = blockIdx.y;
    const int b   = blockIdx.z;
    const int tid = threadIdx.x;
    const int w   = tid >> 5;
    const int l   = tid & 31;
    const int q0  = qt * 64;

    const int lr  = tid >> 1;
    const int lc  = tid & 1;

    const int frow = (l & 7) + ((l >> 3) & 1) * 8;
    const int fch  = l >> 4;

    // ---- prologue: Q tile + stage 0 ----
    {
        const __half* qs = Qs + (size_t)(b * SEQ + q0 + lr) * EMBD + h * HDIM;
        #pragma unroll
        for (int i = 0; i < 4; ++i) {
            const int c = lc * 4 + i;
            const uint32_t o = lr * 128 + ((c ^ (lr & 7)) << 4);
            CP_ASYNC16(sQ + o, qs + c * 8);
        }
    }
    auto load_stage = [&](int kt, int buf) {
        const uint32_t sb = sQ + AT + buf * ASTG;
        const __half* ks = Ks + (size_t)(b * SEQ + kt * 64 + lr) * EMBD + h * HDIM;
        const __half* vs = Vt + (size_t)((b * NHEAD + h) * HDIM + lr) * SEQ + kt * 64;
        #pragma unroll
        for (int i = 0; i < 4; ++i) {
            const int c = lc * 4 + i;
            const uint32_t o = lr * 128 + ((c ^ (lr & 7)) << 4);
            CP_ASYNC16(sb + o,      ks + c * 8);
            CP_ASYNC16(sb + AT + o, vs + c * 8);
        }
    };
    load_stage(0, 0);
    CP_COMMIT();

    float o_[8][4];
    #pragma unroll
    for (int nt = 0; nt < 8; ++nt)
        #pragma unroll
        for (int c = 0; c < 4; ++c) o_[nt][c] = 0.f;
    float mA = -1e30f, mB = -1e30f, lA = 0.f, lB = 0.f;

    const int rA = w * 16 + (l >> 2);
    const int cBase = (l & 3) * 2;

    for (int kt = 0; kt <= qt; ++kt) {
        const int buf = kt & 1;
        CP_WAIT0();
        __syncthreads();
        if (kt < qt) { load_stage(kt + 1, buf ^ 1); CP_COMMIT(); }

        const uint32_t sb = sQ + AT + buf * ASTG;

        // ---- S = Q K^T (fp16) ----
        float s[8][4];
        #pragma unroll
        for (int nt = 0; nt < 8; ++nt)
            #pragma unroll
            for (int c = 0; c < 4; ++c) s[nt][c] = 0.f;

        #pragma unroll
        for (int kk = 0; kk < 4; ++kk) {
            const int cI = kk * 2 + fch;
            uint32_t qf[4], kf[4][4];
            {
                const int qr = w * 16 + frow;
                const uint32_t qa = sQ + qr * 128 + ((cI ^ (qr & 7)) << 4);
                LDSM4(qf, qa);
            }
            #pragma unroll
            for (int p = 0; p < 4; ++p) {
                const int kr = p * 16 + frow;
                const uint32_t ka = sb + kr * 128 + ((cI ^ (kr & 7)) << 4);
                LDSM4(kf[p], ka);
            }
            #pragma unroll
            for (int nt = 0; nt < 8; ++nt) {
                const int p = nt >> 1, o = nt & 1;
                MMA_FP16(s[nt], qf, kf[p][0 + o], kf[p][2 + o]);
            }
        }

        if (kt == qt) {
            #pragma unroll
            for (int nt = 0; nt < 8; ++nt) {
                const int c0 = nt * 8 + cBase;
                if (c0 > rA)         s[nt][0] = -1e30f;
                if (c0 + 1 > rA)     s[nt][1] = -1e30f;
                if (c0 > rA + 8)     s[nt][2] = -1e30f;
                if (c0 + 1 > rA + 8) s[nt][3] = -1e30f;
            }
        }

        // ---- online softmax (registers + quad shfl), log2 domain ----
        float mlA = -1e30f, mlB = -1e30f;
        #pragma unroll
        for (int nt = 0; nt < 8; ++nt) {
            mlA = fmaxf(mlA, fmaxf(s[nt][0], s[nt][1]));
            mlB = fmaxf(mlB, fmaxf(s[nt][2], s[nt][3]));
        }
        mlA = fmaxf(mlA, __shfl_xor_sync(0xffffffffu, mlA, 1));
        mlA = fmaxf(mlA, __shfl_xor_sync(0xffffffffu, mlA, 2));
        mlB = fmaxf(mlB, __shfl_xor_sync(0xffffffffu, mlB, 1));
        mlB = fmaxf(mlB, __shfl_xor_sync(0xffffffffu, mlB, 2));
        const float mAn = fmaxf(mA, mlA);
        const float mBn = fmaxf(mB, mlB);
        const float aAl = exp2f_fast(mA - mAn);
        const float aBl = exp2f_fast(mB - mBn);
        mA = mAn; mB = mBn;

        float sumA = 0.f, sumB = 0.f;
        #pragma unroll
        for (int nt = 0; nt < 8; ++nt) {
            s[nt][0] = exp2f_fast(s[nt][0] - mAn);
            s[nt][1] = exp2f_fast(s[nt][1] - mAn);
            s[nt][2] = exp2f_fast(s[nt][2] - mBn);
            s[nt][3] = exp2f_fast(s[nt][3] - mBn);
            sumA += s[nt][0] + s[nt][1];
            sumB += s[nt][2] + s[nt][3];
        }
        sumA += __shfl_xor_sync(0xffffffffu, sumA, 1);
        sumA += __shfl_xor_sync(0xffffffffu, sumA, 2);
        sumB += __shfl_xor_sync(0xffffffffu, sumB, 1);
        sumB += __shfl_xor_sync(0xffffffffu, sumB, 2);
        lA = lA * aAl + sumA;
        lB = lB * aBl + sumB;

        #pragma unroll
        for (int nt = 0; nt < 8; ++nt) {
            o_[nt][0] *= aAl; o_[nt][1] *= aAl;
            o_[nt][2] *= aBl; o_[nt][3] *= aBl;
        }

        // ---- O += P V (fp16) ----
        #pragma unroll
        for (int kp = 0; kp < 4; ++kp) {
            uint32_t pf[4];
            pf[0] = packh2(s[2 * kp][0],     s[2 * kp][1]);
            pf[1] = packh2(s[2 * kp][2],     s[2 * kp][3]);
            pf[2] = packh2(s[2 * kp + 1][0], s[2 * kp + 1][1]);
            pf[3] = packh2(s[2 * kp + 1][2], s[2 * kp + 1][3]);

            const int cI = kp * 2 + fch;
            uint32_t vf[4][4];
            #pragma unroll
            for (int p = 0; p < 4; ++p) {
                const int vr = p * 16 + frow;
                const uint32_t va = sb + AT + vr * 128 + ((cI ^ (vr & 7)) << 4);
                LDSM4(vf[p], va);
            }
            #pragma unroll
            for (int nt = 0; nt < 8; ++nt) {
                const int p = nt >> 1, o = nt & 1;
                MMA_FP16(o_[nt], pf, vf[p][0 + o], vf[p][2 + o]);
            }
        }
    }

    // ---- epilogue: normalize, split to bf16 hi/lo for out-proj GEMM ----
    const float iA = 1.0f / lA, iB = 1.0f / lB;
    const size_t row0 = (size_t)(b * SEQ + q0 + rA);
    #pragma unroll
    for (int nt = 0; nt < 8; ++nt) {
        const int d = h * HDIM + nt * 8 + cBase;
        uint32_t h0, l0, h1, l1;
        split2(o_[nt][0] * iA, o_[nt][1] * iA, h0, l0);
        split2(o_[nt][2] * iB, o_[nt][3] * iB, h1, l1);
        *(uint32_t*)(Ch + row0 * EMBD + d)       = h0;
        *(uint32_t*)(Cl + row0 * EMBD + d)       = l0;
        *(uint32_t*)(Ch + (row0 + 8) * EMBD + d) = h1;
        *(uint32_t*)(Cl + (row0 + 8) * EMBD + d) = l1;
    }
}

// ---------------------------------------------------------------------------
// prep kernels
// ---------------------------------------------------------------------------
static __device__ __forceinline__ unsigned pack2(float a, float b) {
    __nv_bfloat162 t = __floats2bfloat162_rn(a, b);
    return *reinterpret_cast<unsigned*>(&t);
}
__global__ __launch_bounds__(256) void split_pair(
    const float4* __restrict__ src, uint2* __restrict__ h, uint2* __restrict__ l, int n4)
{
    const int i = blockIdx.x * 256 + threadIdx.x;
    if (i >= n4) return;
    const float4 v = src[i];
    const float hx = __bfloat162float(__float2bfloat16(v.x));
    const float hy = __bfloat162float(__float2bfloat16(v.y));
    const float hz = __bfloat162float(__float2bfloat16(v.z));
    const float hw = __bfloat162float(__float2bfloat16(v.w));
    h[i] = make_uint2(pack2(v.x, v.y), pack2(v.z, v.w));
    l[i] = make_uint2(pack2(v.x - hx, v.y - hy), pack2(v.z - hz, v.w - hw));
}

// Q (scaled) and K slices of qkv -> fp16, layout [tok][1024]
__global__ __launch_bounds__(256) void qk_half(
    const float* __restrict__ qkv, uint2* __restrict__ qh, uint2* __restrict__ kh)
{
    const float QSC = 0.1803368801111244f;   // 0.125 * log2(e)
    const int i = blockIdx.x * 256 + threadIdx.x;
    const int tok = i >> 8, c4 = (i & 255);
    {
        const float4 v = *(const float4*)(qkv + (size_t)tok * 3072 + c4 * 4);
        qh[(size_t)tok * 256 + c4] =
            make_uint2(packh2(v.x * QSC, v.y * QSC), packh2(v.z * QSC, v.w * QSC));
    }
    {
        const float4 v = *(const float4*)(qkv + (size_t)tok * 3072 + 1024 + c4 * 4);
        kh[(size_t)tok * 256 + c4] = make_uint2(packh2(v.x, v.y), packh2(v.z, v.w));
    }
}

// V slice of qkv -> transposed fp16 [b,h,d][t]
__global__ void vt_half(const float* __restrict__ qkv, __half* __restrict__ T)
{
    __shared__ float t[32][33];
    const int t0 = blockIdx.x * 32;
    const int d0 = blockIdx.y * 32;
    const int bh = blockIdx.z;
    const int b  = bh >> 4, h = bh & 15;
    const int x = threadIdx.x, y = threadIdx.y;
    #pragma unroll
    for (int i = 0; i < 32; i += 8)
        t[y + i][x] = qkv[(size_t)(b * SEQ + t0 + y + i) * 3072 + 2048 + h * HDIM + d0 + x];
    __syncthreads();
    #pragma unroll
    for (int i = 0; i < 32; i += 8)
        T[(size_t)(bh * HDIM + d0 + y + i) * SEQ + t0 + x] = __float2half(t[x][y + i]);
}

__global__ void transpose_split(const float* __restrict__ W,
                                __nv_bfloat16* __restrict__ Th,
                                __nv_bfloat16* __restrict__ Tl, int K, int N)
{
    __shared__ float t[32][33];
    const int k0 = blockIdx.y * 32, n0 = blockIdx.x * 32;
    const int x = threadIdx.x, y = threadIdx.y;
    #pragma unroll
    for (int i = 0; i < 32; i += 8)
        t[y + i][x] = W[(size_t)(k0 + y + i) * N + n0 + x];
    __syncthreads();
    #pragma unroll
    for (int i = 0; i < 32; i += 8) {
        const float v = t[x][y + i];
        const __nv_bfloat16 hv = __float2bfloat16(v);
        const size_t o = (size_t)(n0 + y + i) * K + k0 + x;
        Th[o] = hv;
        Tl[o] = __float2bfloat16(v - __bfloat162float(hv));
    }
}

// ---------------------------------------------------------------------------
extern "C" void kernel_launch(void* const* d_in, const int* in_sizes, int n_in,
                              void* d_out, int out_size)
{
    const float* x     = (const float*)d_in[0];
    const float* w_qkv = (const float*)d_in[1];
    const float* b_qkv = (const float*)d_in[2];
    const float* w_out = (const float*)d_in[3];
    const float* b_out = (const float*)d_in[4];
    float* out = (float*)d_out;

    float* qkv;
    __nv_bfloat16 *xh, *xl, *ch, *cl, *wqh, *wql, *woh, *wol;
    __half *qs, *ks, *vt;
    cudaGetSymbolAddress((void**)&qkv, g_qkv);
    cudaGetSymbolAddress((void**)&xh, g_xh);
    cudaGetSymbolAddress((void**)&xl, g_xl);
    cudaGetSymbolAddress((void**)&ch, g_ch);
    cudaGetSymbolAddress((void**)&cl, g_cl);
    cudaGetSymbolAddress((void**)&wqh, g_wqh);
    cudaGetSymbolAddress((void**)&wql, g_wql);
    cudaGetSymbolAddress((void**)&woh, g_woh);
    cudaGetSymbolAddress((void**)&wol, g_wol);
    cudaGetSymbolAddress((void**)&qs, g_qs);
    cudaGetSymbolAddress((void**)&ks, g_ks);
    cudaGetSymbolAddress((void**)&vt, g_vt);

    cudaFuncSetAttribute(gemm_mma, cudaFuncAttributeMaxDynamicSharedMemorySize, GSMEM);
    cudaFuncSetAttribute(attn_mma, cudaFuncAttributeMaxDynamicSharedMemorySize, ASMEM);

    const int n4 = TOK * EMBD / 4;

    split_pair<<<n4 / 256, 256>>>((const float4*)x, (uint2*)xh, (uint2*)xl, n4);
    transpose_split<<<dim3(3 * EMBD / 32, EMBD / 32), dim3(32, 8)>>>(w_qkv, wqh, wql, EMBD, 3 * EMBD);
    transpose_split<<<dim3(EMBD / 32, EMBD / 32), dim3(32, 8)>>>(w_out, woh, wol, EMBD, EMBD);

    // 1) qkv = x @ w_qkv + b_qkv   (R9 proven config)
    gemm_mma<<<dim3(3 * EMBD / 128, TOK / 128), 256, GSMEM>>>(xh, xl, wqh, wql, b_qkv, qkv, 3 * EMBD);

    // 2) prep attention operands (fp16)
    qk_half<<<TOK, 256>>>(qkv, (uint2*)qs, (uint2*)ks);
    vt_half<<<dim3(SEQ / 32, HDIM / 32, 4 * NHEAD), dim3(32, 8)>>>(qkv, vt);

    // 3) causal flash attention (single-pass fp16 HMMA)
    attn_mma<<<dim3(SEQ / 64, NHEAD, 4), 128, ASMEM>>>(qs, ks, vt, ch, cl);

    // 4) out = ctx @ w_out + b_out
    gemm_mma<<<dim3(EMBD / 128, TOK / 128), 256, GSMEM>>>(ch, cl, woh, wol, b_out, out, EMBD);
}

// round 14
// speedup vs baseline: 1.6560x; 1.2529x over previous
#include <cuda_runtime.h>
#include <cuda_bf16.h>
#include <cuda_fp16.h>
#include <cstdint>
#include <math.h>

#define TOK   8192
#define EMBD  1024
#define SEQ   2048
#define NHEAD 16
#define HDIM  64

// ---------------- scratch (allocation-free rule: device globals) ----------
__device__ float g_qkv[(size_t)TOK * 3 * EMBD];
__device__ __half g_xh[(size_t)TOK * EMBD];           // x hi (fp16 split)
__device__ __half g_xl[(size_t)TOK * EMBD];           // x lo residual
__device__ __half g_ch[(size_t)TOK * EMBD];           // ctx hi
__device__ __half g_cl[(size_t)TOK * EMBD];           // ctx lo
__device__ __half g_wq[(size_t)3 * EMBD * EMBD];      // w_qkv^T fp16 [N][K]
__device__ __half g_wo[(size_t)EMBD * EMBD];          // w_out^T fp16 [N][K]
// attention operands (fp16, prepped once)
__device__ __half g_qs[(size_t)TOK * EMBD];           // scaled Q [tok][h*64+d]
__device__ __half g_ks[(size_t)TOK * EMBD];           // K        [tok][h*64+d]
__device__ __half g_vt[(size_t)TOK * EMBD];           // V^T      [b,h,d][t]

// ---------------- helpers ---------------------------------------------
__device__ __forceinline__ uint32_t smem_u32(const void* p) {
    uint32_t a;
    asm("{ .reg .u64 t; cvta.to.shared.u64 t, %1; cvt.u32.u64 %0, t; }" : "=r"(a) : "l"(p));
    return a;
}

#define LDSM4(r, a) \
    asm volatile("ldmatrix.sync.aligned.m8n8.x4.shared.b16 {%0,%1,%2,%3}, [%4];" \
        : "=r"((r)[0]), "=r"((r)[1]), "=r"((r)[2]), "=r"((r)[3]) : "r"(a))

#define MMA_FP16(c, a, b0, b1) \
    asm volatile("mma.sync.aligned.m16n8k16.row.col.f32.f16.f16.f32 " \
        "{%0,%1,%2,%3},{%4,%5,%6,%7},{%8,%9},{%0,%1,%2,%3};" \
        : "+f"((c)[0]), "+f"((c)[1]), "+f"((c)[2]), "+f"((c)[3]) \
        : "r"((a)[0]), "r"((a)[1]), "r"((a)[2]), "r"((a)[3]), "r"(b0), "r"(b1))

#define CP_ASYNC16(so, gp) \
    asm volatile("cp.async.cg.shared.global [%0], [%1], 16;" :: "r"(so), "l"(gp) : "memory")
#define CP_COMMIT() asm volatile("cp.async.commit_group;" ::: "memory")
#define CP_WAIT0()  asm volatile("cp.async.wait_group 0;" ::: "memory")

// fast exp2 on fma pipe (arg <= 0, clamped), rel err ~2e-5
__device__ __forceinline__ float exp2f_fast(float t) {
    t = fmaxf(t, -100.0f);
    float fi = floorf(t);
    float f  = t - fi;
    float p  = 1.33335581e-3f;
    p = fmaf(p, f, 9.61812910e-3f);
    p = fmaf(p, f, 5.55041087e-2f);
    p = fmaf(p, f, 2.40226507e-1f);
    p = fmaf(p, f, 6.93147182e-1f);
    p = fmaf(p, f, 1.0f);
    return __int_as_float(((int)fi + 127) << 23) * p;
}

__device__ __forceinline__ uint32_t packh2(float x, float y) {
    __half2 t = __floats2half2_rn(x, y);
    return *reinterpret_cast<uint32_t*>(&t);
}

// split x,y into fp16x2 hi + fp16x2 lo residual
__device__ __forceinline__ void split2h(float x, float y, uint32_t& hi, uint32_t& lo) {
    __half2 h2 = __floats2half2_rn(x, y);
    float2 hf = __half22float2(h2);
    __half2 l2 = __floats2half2_rn(x - hf.x, y - hf.y);
    hi = *reinterpret_cast<uint32_t*>(&h2);
    lo = *reinterpret_cast<uint32_t*>(&l2);
}

// ---------------------------------------------------------------------------
// mma.sync fp16 2-term GEMM: C[M,N] = (Ah+Al)[M,1024] @ B[N,1024]^T + bias.
// A split hi/lo fp16 (exact to 22 bits), B single fp16. Products exact in
// fp32 accumulator -> error ~ eps_fp16(B) only.
// Block 128x128, warp 64x32, K-slab 32, 2-stage cp.async, 2 blocks/SM.
// ---------------------------------------------------------------------------
#define LDB    80
#define TILEB  (128 * LDB)          // 10240 B
#define GSTAGE (3 * TILEB)          // Ah | Al | B = 30720 B
#define GSMEM  (2 * GSTAGE)         // 61440 B

__global__ __launch_bounds__(256) void gemm_mma(
    const __half* __restrict__ Ah, const __half* __restrict__ Al,
    const __half* __restrict__ B,
    const float* __restrict__ bias, float* __restrict__ C, int N)
{
    extern __shared__ char smem[];
    const uint32_t sbase = smem_u32(smem);
    const int tid = threadIdx.x;
    const int wid = tid >> 5;
    const int l   = tid & 31;
    const int m0  = blockIdx.y * 128;
    const int n0  = blockIdx.x * 128;
    const int wm  = (wid >> 2) * 64;
    const int wn  = (wid & 3) * 32;

    const __half* srcs[3] = {
        Ah + (size_t)m0 * 1024, Al + (size_t)m0 * 1024, B + (size_t)n0 * 1024 };

    const int frow = (l & 7) + ((l >> 3) & 1) * 8;
    const int fkb  = (l >> 4) * 16;

    float acc[4][4][4];
    #pragma unroll
    for (int a = 0; a < 4; ++a)
        #pragma unroll
        for (int b = 0; b < 4; ++b)
            #pragma unroll
            for (int c = 0; c < 4; ++c) acc[a][b][c] = 0.f;

    auto load_stage = [&](int ks, int buf) {
        const uint32_t sb = sbase + buf * GSTAGE;
        const int kc = ks * 32;
        #pragma unroll
        for (int t = 0; t < 3; ++t) {
            #pragma unroll
            for (int j = 0; j < 2; ++j) {
                const int chunk = j * 256 + tid;        // 0..511
                const int row = chunk >> 2, seg = chunk & 3;
                const uint32_t so = sb + t * TILEB + row * LDB + seg * 16;
                CP_ASYNC16(so, srcs[t] + (size_t)row * 1024 + kc + seg * 8);
            }
        }
    };

    load_stage(0, 0);
    CP_COMMIT();

    for (int ks = 0; ks < 32; ++ks) {
        const int buf = ks & 1;
        CP_WAIT0();
        __syncthreads();
        if (ks + 1 < 32) { load_stage(ks + 1, buf ^ 1); CP_COMMIT(); }

        const uint32_t sb = sbase + buf * GSTAGE;
        #pragma unroll
        for (int kk = 0; kk < 2; ++kk) {
            const uint32_t kbo = kk * 32 + fkb;
            uint32_t ah[4][4], al_[4][4], bh[2][4];
            #pragma unroll
            for (int mt = 0; mt < 4; ++mt) {
                const uint32_t addr = sb + (wm + mt * 16 + frow) * LDB + kbo;
                LDSM4(ah[mt], addr);
                LDSM4(al_[mt], addr + TILEB);
            }
            #pragma unroll
            for (int p = 0; p < 2; ++p) {
                const uint32_t addr = sb + 2 * TILEB + (wn + p * 16 + frow) * LDB + kbo;
                LDSM4(bh[p], addr);
            }
            #pragma unroll
            for (int mt = 0; mt < 4; ++mt)
                #pragma unroll
                for (int nt = 0; nt < 4; ++nt) {
                    const int p = nt >> 1, o = nt & 1;
                    MMA_FP16(acc[mt][nt], ah[mt],  bh[p][0 + o], bh[p][2 + o]);
                    MMA_FP16(acc[mt][nt], al_[mt], bh[p][0 + o], bh[p][2 + o]);
                }
        }
    }

    __syncthreads();
    const int er = l >> 2, ec = (l & 3) * 2;
    #pragma unroll
    for (int mt = 0; mt < 4; ++mt) {
        #pragma unroll
        for (int nt = 0; nt < 4; ++nt) {
            const int m = m0 + wm + mt * 16 + er;
            const int n = n0 + wn + nt * 8 + ec;
            const float b0 = __ldg(bias + n), b1 = __ldg(bias + n + 1);
            float2 v0 = { acc[mt][nt][0] + b0, acc[mt][nt][1] + b1 };
            float2 v1 = { acc[mt][nt][2] + b0, acc[mt][nt][3] + b1 };
            *(float2*)(C + (size_t)m * N + n)       = v0;
            *(float2*)(C + (size_t)(m + 8) * N + n) = v1;
        }
    }
}

// ---------------------------------------------------------------------------
// HMMA flash attention, single-pass fp16 (fp32 accumulate) — R12 proven.
// ---------------------------------------------------------------------------
#define AT    8192                  // one 64x64 fp16 tile
#define ASTG  (2 * AT)              // K,V per stage
#define ASMEM (AT + 2 * ASTG)       // 40960 B

__global__ __launch_bounds__(128) void attn_mma(
    const __half* __restrict__ Qs, const __half* __restrict__ Ks,
    const __half* __restrict__ Vt,
    __half* __restrict__ Ch, __half* __restrict__ Cl)
{
    extern __shared__ char smem[];
    const uint32_t sQ = smem_u32(smem);

    const int qt  = gridDim.x - 1 - blockIdx.x;   // heavy tiles first
    const int h   = blockIdx.y;
    const int b   = blockIdx.z;
    const int tid = threadIdx.x;
    const int w   = tid >> 5;
    const int l   = tid & 31;
    const int q0  = qt * 64;

    const int lr  = tid >> 1;
    const int lc  = tid & 1;

    const int frow = (l & 7) + ((l >> 3) & 1) * 8;
    const int fch  = l >> 4;

    {
        const __half* qs = Qs + (size_t)(b * SEQ + q0 + lr) * EMBD + h * HDIM;
        #pragma unroll
        for (int i = 0; i < 4; ++i) {
            const int c = lc * 4 + i;
            const uint32_t o = lr * 128 + ((c ^ (lr & 7)) << 4);
            CP_ASYNC16(sQ + o, qs + c * 8);
        }
    }
    auto load_stage = [&](int kt, int buf) {
        const uint32_t sb = sQ + AT + buf * ASTG;
        const __half* ks = Ks + (size_t)(b * SEQ + kt * 64 + lr) * EMBD + h * HDIM;
        const __half* vs = Vt + (size_t)((b * NHEAD + h) * HDIM + lr) * SEQ + kt * 64;
        #pragma unroll
        for (int i = 0; i < 4; ++i) {
            const int c = lc * 4 + i;
            const uint32_t o = lr * 128 + ((c ^ (lr & 7)) << 4);
            CP_ASYNC16(sb + o,      ks + c * 8);
            CP_ASYNC16(sb + AT + o, vs + c * 8);
        }
    };
    load_stage(0, 0);
    CP_COMMIT();

    float o_[8][4];
    #pragma unroll
    for (int nt = 0; nt < 8; ++nt)
        #pragma unroll
        for (int c = 0; c < 4; ++c) o_[nt][c] = 0.f;
    float mA = -1e30f, mB = -1e30f, lA = 0.f, lB = 0.f;

    const int rA = w * 16 + (l >> 2);
    const int cBase = (l & 3) * 2;

    for (int kt = 0; kt <= qt; ++kt) {
        const int buf = kt & 1;
        CP_WAIT0();
        __syncthreads();
        if (kt < qt) { load_stage(kt + 1, buf ^ 1); CP_COMMIT(); }

        const uint32_t sb = sQ + AT + buf * ASTG;

        float s[8][4];
        #pragma unroll
        for (int nt = 0; nt < 8; ++nt)
            #pragma unroll
            for (int c = 0; c < 4; ++c) s[nt][c] = 0.f;

        #pragma unroll
        for (int kk = 0; kk < 4; ++kk) {
            const int cI = kk * 2 + fch;
            uint32_t qf[4], kf[4][4];
            {
                const int qr = w * 16 + frow;
                const uint32_t qa = sQ + qr * 128 + ((cI ^ (qr & 7)) << 4);
                LDSM4(qf, qa);
            }
            #pragma unroll
            for (int p = 0; p < 4; ++p) {
                const int kr = p * 16 + frow;
                const uint32_t ka = sb + kr * 128 + ((cI ^ (kr & 7)) << 4);
                LDSM4(kf[p], ka);
            }
            #pragma unroll
            for (int nt = 0; nt < 8; ++nt) {
                const int p = nt >> 1, o = nt & 1;
                MMA_FP16(s[nt], qf, kf[p][0 + o], kf[p][2 + o]);
            }
        }

        if (kt == qt) {
            #pragma unroll
            for (int nt = 0; nt < 8; ++nt) {
                const int c0 = nt * 8 + cBase;
                if (c0 > rA)         s[nt][0] = -1e30f;
                if (c0 + 1 > rA)     s[nt][1] = -1e30f;
                if (c0 > rA + 8)     s[nt][2] = -1e30f;
                if (c0 + 1 > rA + 8) s[nt][3] = -1e30f;
            }
        }

        float mlA = -1e30f, mlB = -1e30f;
        #pragma unroll
        for (int nt = 0; nt < 8; ++nt) {
            mlA = fmaxf(mlA, fmaxf(s[nt][0], s[nt][1]));
            mlB = fmaxf(mlB, fmaxf(s[nt][2], s[nt][3]));
        }
        mlA = fmaxf(mlA, __shfl_xor_sync(0xffffffffu, mlA, 1));
        mlA = fmaxf(mlA, __shfl_xor_sync(0xffffffffu, mlA, 2));
        mlB = fmaxf(mlB, __shfl_xor_sync(0xffffffffu, mlB, 1));
        mlB = fmaxf(mlB, __shfl_xor_sync(0xffffffffu, mlB, 2));
        const float mAn = fmaxf(mA, mlA);
        const float mBn = fmaxf(mB, mlB);
        const float aAl = exp2f_fast(mA - mAn);
        const float aBl = exp2f_fast(mB - mBn);
        mA = mAn; mB = mBn;

        float sumA = 0.f, sumB = 0.f;
        #pragma unroll
        for (int nt = 0; nt < 8; ++nt) {
            s[nt][0] = exp2f_fast(s[nt][0] - mAn);
            s[nt][1] = exp2f_fast(s[nt][1] - mAn);
            s[nt][2] = exp2f_fast(s[nt][2] - mBn);
            s[nt][3] = exp2f_fast(s[nt][3] - mBn);
            sumA += s[nt][0] + s[nt][1];
            sumB += s[nt][2] + s[nt][3];
        }
        sumA += __shfl_xor_sync(0xffffffffu, sumA, 1);
        sumA += __shfl_xor_sync(0xffffffffu, sumA, 2);
        sumB += __shfl_xor_sync(0xffffffffu, sumB, 1);
        sumB += __shfl_xor_sync(0xffffffffu, sumB, 2);
        lA = lA * aAl + sumA;
        lB = lB * aBl + sumB;

        #pragma unroll
        for (int nt = 0; nt < 8; ++nt) {
            o_[nt][0] *= aAl; o_[nt][1] *= aAl;
            o_[nt][2] *= aBl; o_[nt][3] *= aBl;
        }

        #pragma unroll
        for (int kp = 0; kp < 4; ++kp) {
            uint32_t pf[4];
            pf[0] = packh2(s[2 * kp][0],     s[2 * kp][1]);
            pf[1] = packh2(s[2 * kp][2],     s[2 * kp][3]);
            pf[2] = packh2(s[2 * kp + 1][0], s[2 * kp + 1][1]);
            pf[3] = packh2(s[2 * kp + 1][2], s[2 * kp + 1][3]);

            const int cI = kp * 2 + fch;
            uint32_t vf[4][4];
            #pragma unroll
            for (int p = 0; p < 4; ++p) {
                const int vr = p * 16 + frow;
                const uint32_t va = sb + AT + vr * 128 + ((cI ^ (vr & 7)) << 4);
                LDSM4(vf[p], va);
            }
            #pragma unroll
            for (int nt = 0; nt < 8; ++nt) {
                const int p = nt >> 1, o = nt & 1;
                MMA_FP16(o_[nt], pf, vf[p][0 + o], vf[p][2 + o]);
            }
        }
    }

    // epilogue: normalize, split to fp16 hi/lo for the out-proj GEMM
    const float iA = 1.0f / lA, iB = 1.0f / lB;
    const size_t row0 = (size_t)(b * SEQ + q0 + rA);
    #pragma unroll
    for (int nt = 0; nt < 8; ++nt) {
        const int d = h * HDIM + nt * 8 + cBase;
        uint32_t h0, l0, h1, l1;
        split2h(o_[nt][0] * iA, o_[nt][1] * iA, h0, l0);
        split2h(o_[nt][2] * iB, o_[nt][3] * iB, h1, l1);
        *(uint32_t*)(Ch + row0 * EMBD + d)       = h0;
        *(uint32_t*)(Cl + row0 * EMBD + d)       = l0;
        *(uint32_t*)(Ch + (row0 + 8) * EMBD + d) = h1;
        *(uint32_t*)(Cl + (row0 + 8) * EMBD + d) = l1;
    }
}

// ---------------------------------------------------------------------------
// prep kernels
// ---------------------------------------------------------------------------
// fp32 -> fp16 hi + lo residual, vectorized by 4
__global__ __launch_bounds__(256) void split_pair_h(
    const float4* __restrict__ src, uint2* __restrict__ h, uint2* __restrict__ l, int n4)
{
    const int i = blockIdx.x * 256 + threadIdx.x;
    if (i >= n4) return;
    const float4 v = src[i];
    uint32_t h0, l0, h1, l1;
    split2h(v.x, v.y, h0, l0);
    split2h(v.z, v.w, h1, l1);
    h[i] = make_uint2(h0, h1);
    l[i] = make_uint2(l0, l1);
}

// W[K,N] fp32 -> W^T fp16 [N][K] (single precision term)
__global__ void transpose_half(const float* __restrict__ W,
                               __half* __restrict__ T, int K, int N)
{
    __shared__ float t[32][33];
    const int k0 = blockIdx.y * 32, n0 = blockIdx.x * 32;
    const int x = threadIdx.x, y = threadIdx.y;
    #pragma unroll
    for (int i = 0; i < 32; i += 8)
        t[y + i][x] = W[(size_t)(k0 + y + i) * N + n0 + x];
    __syncthreads();
    #pragma unroll
    for (int i = 0; i < 32; i += 8)
        T[(size_t)(n0 + y + i) * K + k0 + x] = __float2half(t[x][y + i]);
}

// Q (scaled) and K slices of qkv -> fp16, layout [tok][1024]
__global__ __launch_bounds__(256) void qk_half(
    const float* __restrict__ qkv, uint2* __restrict__ qh, uint2* __restrict__ kh)
{
    const float QSC = 0.1803368801111244f;   // 0.125 * log2(e)
    const int i = blockIdx.x * 256 + threadIdx.x;
    const int tok = i >> 8, c4 = (i & 255);
    {
        const float4 v = *(const float4*)(qkv + (size_t)tok * 3072 + c4 * 4);
        qh[(size_t)tok * 256 + c4] =
            make_uint2(packh2(v.x * QSC, v.y * QSC), packh2(v.z * QSC, v.w * QSC));
    }
    {
        const float4 v = *(const float4*)(qkv + (size_t)tok * 3072 + 1024 + c4 * 4);
        kh[(size_t)tok * 256 + c4] = make_uint2(packh2(v.x, v.y), packh2(v.z, v.w));
    }
}

// V slice of qkv -> transposed fp16 [b,h,d][t]
__global__ void vt_half(const float* __restrict__ qkv, __half* __restrict__ T)
{
    __shared__ float t[32][33];
    const int t0 = blockIdx.x * 32;
    const int d0 = blockIdx.y * 32;
    const int bh = blockIdx.z;
    const int b  = bh >> 4, h = bh & 15;
    const int x = threadIdx.x, y = threadIdx.y;
    #pragma unroll
    for (int i = 0; i < 32; i += 8)
        t[y + i][x] = qkv[(size_t)(b * SEQ + t0 + y + i) * 3072 + 2048 + h * HDIM + d0 + x];
    __syncthreads();
    #pragma unroll
    for (int i = 0; i < 32; i += 8)
        T[(size_t)(bh * HDIM + d0 + y + i) * SEQ + t0 + x] = __float2half(t[x][y + i]);
}

// ---------------------------------------------------------------------------
extern "C" void kernel_launch(void* const* d_in, const int* in_sizes, int n_in,
                              void* d_out, int out_size)
{
    const float* x     = (const float*)d_in[0];
    const float* w_qkv = (const float*)d_in[1];
    const float* b_qkv = (const float*)d_in[2];
    const float* w_out = (const float*)d_in[3];
    const float* b_out = (const float*)d_in[4];
    float* out = (float*)d_out;

    float* qkv;
    __half *xh, *xl, *ch, *cl, *wq, *wo, *qs, *ks, *vt;
    cudaGetSymbolAddress((void**)&qkv, g_qkv);
    cudaGetSymbolAddress((void**)&xh, g_xh);
    cudaGetSymbolAddress((void**)&xl, g_xl);
    cudaGetSymbolAddress((void**)&ch, g_ch);
    cudaGetSymbolAddress((void**)&cl, g_cl);
    cudaGetSymbolAddress((void**)&wq, g_wq);
    cudaGetSymbolAddress((void**)&wo, g_wo);
    cudaGetSymbolAddress((void**)&qs, g_qs);
    cudaGetSymbolAddress((void**)&ks, g_ks);
    cudaGetSymbolAddress((void**)&vt, g_vt);

    cudaFuncSetAttribute(gemm_mma, cudaFuncAttributeMaxDynamicSharedMemorySize, GSMEM);
    cudaFuncSetAttribute(attn_mma, cudaFuncAttributeMaxDynamicSharedMemorySize, ASMEM);

    const int n4 = TOK * EMBD / 4;

    split_pair_h<<<n4 / 256, 256>>>((const float4*)x, (uint2*)xh, (uint2*)xl, n4);
    transpose_half<<<dim3(3 * EMBD / 32, EMBD / 32), dim3(32, 8)>>>(w_qkv, wq, EMBD, 3 * EMBD);
    transpose_half<<<dim3(EMBD / 32, EMBD / 32), dim3(32, 8)>>>(w_out, wo, EMBD, EMBD);

    // 1) qkv = x @ w_qkv + b_qkv   (fp16 2-term)
    gemm_mma<<<dim3(3 * EMBD / 128, TOK / 128), 256, GSMEM>>>(xh, xl, wq, b_qkv, qkv, 3 * EMBD);

    // 2) prep attention operands (fp16)
    qk_half<<<TOK, 256>>>(qkv, (uint2*)qs, (uint2*)ks);
    vt_half<<<dim3(SEQ / 32, HDIM / 32, 4 * NHEAD), dim3(32, 8)>>>(qkv, vt);

    // 3) causal flash attention (single-pass fp16 HMMA)
    attn_mma<<<dim3(SEQ / 64, NHEAD, 4), 128, ASMEM>>>(qs, ks, vt, ch, cl);

    // 4) out = ctx @ w_out + b_out  (fp16 2-term)
    gemm_mma<<<dim3(EMBD / 128, TOK / 128), 256, GSMEM>>>(ch, cl, wo, b_out, out, EMBD);
}

// round 16
// speedup vs baseline: 1.7483x; 1.0557x over previous
#include <cuda_runtime.h>
#include <cuda_fp16.h>
#include <cstdint>
#include <math.h>

#define TOK   8192
#define EMBD  1024
#define SEQ   2048
#define NHEAD 16
#define HDIM  64

// ---------------- scratch (allocation-free rule: device globals) ----------
__device__ __half g_xh[(size_t)TOK * EMBD];           // x hi (fp16 split)
__device__ __half g_xl[(size_t)TOK * EMBD];           // x lo residual
__device__ __half g_ch[(size_t)TOK * EMBD];           // ctx hi
__device__ __half g_cl[(size_t)TOK * EMBD];           // ctx lo
__device__ __half g_wq[(size_t)3 * EMBD * EMBD];      // w_qkv^T fp16 [N][K]
__device__ __half g_wo[(size_t)EMBD * EMBD];          // w_out^T fp16 [N][K]
// attention operands (fp16, written by fused QKV epilogue)
__device__ __half g_qs[(size_t)TOK * EMBD];           // scaled Q [tok][h*64+d]
__device__ __half g_ks[(size_t)TOK * EMBD];           // K        [tok][h*64+d]
__device__ __half g_vh[(size_t)TOK * EMBD];           // V        [tok][h*64+d]
__device__ __half g_vt[(size_t)TOK * EMBD];           // V^T      [b,h,d][t]

// ---------------- helpers ---------------------------------------------
__device__ __forceinline__ uint32_t smem_u32(const void* p) {
    uint32_t a;
    asm("{ .reg .u64 t; cvta.to.shared.u64 t, %1; cvt.u32.u64 %0, t; }" : "=r"(a) : "l"(p));
    return a;
}

#define LDSM4(r, a) \
    asm volatile("ldmatrix.sync.aligned.m8n8.x4.shared.b16 {%0,%1,%2,%3}, [%4];" \
        : "=r"((r)[0]), "=r"((r)[1]), "=r"((r)[2]), "=r"((r)[3]) : "r"(a))

#define MMA_FP16(c, a, b0, b1) \
    asm volatile("mma.sync.aligned.m16n8k16.row.col.f32.f16.f16.f32 " \
        "{%0,%1,%2,%3},{%4,%5,%6,%7},{%8,%9},{%0,%1,%2,%3};" \
        : "+f"((c)[0]), "+f"((c)[1]), "+f"((c)[2]), "+f"((c)[3]) \
        : "r"((a)[0]), "r"((a)[1]), "r"((a)[2]), "r"((a)[3]), "r"(b0), "r"(b1))

#define CP_ASYNC16(so, gp) \
    asm volatile("cp.async.cg.shared.global [%0], [%1], 16;" :: "r"(so), "l"(gp) : "memory")
#define CP_COMMIT() asm volatile("cp.async.commit_group;" ::: "memory")
#define CP_WAIT0()  asm volatile("cp.async.wait_group 0;" ::: "memory")
#define CP_WAIT1()  asm volatile("cp.async.wait_group 1;" ::: "memory")

// fast exp2 on fma pipe (arg <= 0, clamped), rel err ~2e-5
__device__ __forceinline__ float exp2f_fast(float t) {
    t = fmaxf(t, -100.0f);
    float fi = floorf(t);
    float f  = t - fi;
    float p  = 1.33335581e-3f;
    p = fmaf(p, f, 9.61812910e-3f);
    p = fmaf(p, f, 5.55041087e-2f);
    p = fmaf(p, f, 2.40226507e-1f);
    p = fmaf(p, f, 6.93147182e-1f);
    p = fmaf(p, f, 1.0f);
    return __int_as_float(((int)fi + 127) << 23) * p;
}

__device__ __forceinline__ uint32_t packh2(float x, float y) {
    __half2 t = __floats2half2_rn(x, y);
    return *reinterpret_cast<uint32_t*>(&t);
}

__device__ __forceinline__ void split2h(float x, float y, uint32_t& hi, uint32_t& lo) {
    __half2 h2 = __floats2half2_rn(x, y);
    float2 hf = __half22float2(h2);
    __half2 l2 = __floats2half2_rn(x - hf.x, y - hf.y);
    hi = *reinterpret_cast<uint32_t*>(&h2);
    lo = *reinterpret_cast<uint32_t*>(&l2);
}

// ---------------------------------------------------------------------------
// mma.sync fp16 2-term GEMM: C = (Ah+Al)[M,1024] @ B[N,1024]^T + bias.
// Block 128x128, warp 64x32, K-slab 32, 3-stage cp.async ring, 2 blocks/SM.
// mode 0: C fp32 + bias. mode 1 (fused qkv): per-region fp16 stores
//         (q*QSC -> Q, k -> Kd, v -> V), region = n0/1024, uniform per block.
// ---------------------------------------------------------------------------
#define LDB    80
#define TILEB  (128 * LDB)          // 10240 B
#define GSTAGE (3 * TILEB)          // Ah | Al | B = 30720 B
#define GSMEM  (3 * GSTAGE)         // 92160 B

__global__ __launch_bounds__(256) void gemm_mma(
    const __half* __restrict__ Ah, const __half* __restrict__ Al,
    const __half* __restrict__ B, const float* __restrict__ bias,
    float* __restrict__ C, __half* __restrict__ Q, __half* __restrict__ Kd,
    __half* __restrict__ V, int N, int mode)
{
    extern __shared__ char smem[];
    const uint32_t sbase = smem_u32(smem);
    const int tid = threadIdx.x;
    const int wid = tid >> 5;
    const int l   = tid & 31;
    const int m0  = blockIdx.y * 128;
    const int n0  = blockIdx.x * 128;
    const int wm  = (wid >> 2) * 64;
    const int wn  = (wid & 3) * 32;

    const __half* srcs[3] = {
        Ah + (size_t)m0 * 1024, Al + (size_t)m0 * 1024, B + (size_t)n0 * 1024 };

    const int frow = (l & 7) + ((l >> 3) & 1) * 8;
    const int fkb  = (l >> 4) * 16;

    float acc[4][4][4];
    #pragma unroll
    for (int a = 0; a < 4; ++a)
        #pragma unroll
        for (int b = 0; b < 4; ++b)
            #pragma unroll
            for (int c = 0; c < 4; ++c) acc[a][b][c] = 0.f;

    auto load_stage = [&](int ks) {
        const uint32_t sb = sbase + (ks % 3) * GSTAGE;
        const int kc = ks * 32;
        #pragma unroll
        for (int t = 0; t < 3; ++t) {
            #pragma unroll
            for (int j = 0; j < 2; ++j) {
                const int chunk = j * 256 + tid;        // 0..511
                const int row = chunk >> 2, seg = chunk & 3;
                const uint32_t so = sb + t * TILEB + row * LDB + seg * 16;
                CP_ASYNC16(so, srcs[t] + (size_t)row * 1024 + kc + seg * 8);
            }
        }
    };

    load_stage(0); CP_COMMIT();
    load_stage(1); CP_COMMIT();

    for (int ks = 0; ks < 32; ++ks) {
        if (ks + 2 < 32) CP_WAIT1(); else CP_WAIT0();
        __syncthreads();
        if (ks + 2 < 32) { load_stage(ks + 2); CP_COMMIT(); }

        const uint32_t sb = sbase + (ks % 3) * GSTAGE;
        #pragma unroll
        for (int kk = 0; kk < 2; ++kk) {
            const uint32_t kbo = kk * 32 + fkb;
            uint32_t ah[4][4], al_[4][4], bh[2][4];
            #pragma unroll
            for (int mt = 0; mt < 4; ++mt) {
                const uint32_t addr = sb + (wm + mt * 16 + frow) * LDB + kbo;
                LDSM4(ah[mt], addr);
                LDSM4(al_[mt], addr + TILEB);
            }
            #pragma unroll
            for (int p = 0; p < 2; ++p) {
                const uint32_t addr = sb + 2 * TILEB + (wn + p * 16 + frow) * LDB + kbo;
                LDSM4(bh[p], addr);
            }
            #pragma unroll
            for (int mt = 0; mt < 4; ++mt)
                #pragma unroll
                for (int nt = 0; nt < 4; ++nt) {
                    const int p = nt >> 1, o = nt & 1;
                    MMA_FP16(acc[mt][nt], ah[mt],  bh[p][0 + o], bh[p][2 + o]);
                    MMA_FP16(acc[mt][nt], al_[mt], bh[p][0 + o], bh[p][2 + o]);
                }
        }
    }

    __syncthreads();
    const int er = l >> 2, ec = (l & 3) * 2;

    if (mode == 0) {
        #pragma unroll
        for (int mt = 0; mt < 4; ++mt) {
            #pragma unroll
            for (int nt = 0; nt < 4; ++nt) {
                const int m = m0 + wm + mt * 16 + er;
                const int n = n0 + wn + nt * 8 + ec;
                const float b0 = __ldg(bias + n), b1 = __ldg(bias + n + 1);
                float2 v0 = { acc[mt][nt][0] + b0, acc[mt][nt][1] + b1 };
                float2 v1 = { acc[mt][nt][2] + b0, acc[mt][nt][3] + b1 };
                *(float2*)(C + (size_t)m * N + n)       = v0;
                *(float2*)(C + (size_t)(m + 8) * N + n) = v1;
            }
        }
    } else {
        // fused qkv epilogue: region uniform per block
        const int region = n0 >> 10;                 // 0=q 1=k 2=v
        const float QSC = 0.1803368801111244f;       // 0.125*log2(e)
        const float sc = (region == 0) ? QSC : 1.0f;
        __half* dst = (region == 0) ? Q : (region == 1 ? Kd : V);
        const int nb = n0 & 1023;
        #pragma unroll
        for (int mt = 0; mt < 4; ++mt) {
            #pragma unroll
            for (int nt = 0; nt < 4; ++nt) {
                const int m = m0 + wm + mt * 16 + er;
                const int n = n0 + wn + nt * 8 + ec;
                const int nl = nb + wn + nt * 8 + ec;
                const float b0 = __ldg(bias + n), b1 = __ldg(bias + n + 1);
                const uint32_t h0 = packh2((acc[mt][nt][0] + b0) * sc,
                                           (acc[mt][nt][1] + b1) * sc);
                const uint32_t h1 = packh2((acc[mt][nt][2] + b0) * sc,
                                           (acc[mt][nt][3] + b1) * sc);
                *(uint32_t*)(dst + (size_t)m * 1024 + nl)       = h0;
                *(uint32_t*)(dst + (size_t)(m + 8) * 1024 + nl) = h1;
            }
        }
    }
}

// ---------------------------------------------------------------------------
// HMMA flash attention, single-pass fp16 (fp32 accumulate) — proven config.
// ---------------------------------------------------------------------------
#define AT    8192                  // one 64x64 fp16 tile
#define ASTG  (2 * AT)              // K,V per stage
#define ASMEM (AT + 2 * ASTG)       // 40960 B

__global__ __launch_bounds__(128) void attn_mma(
    const __half* __restrict__ Qs, const __half* __restrict__ Ks,
    const __half* __restrict__ Vt,
    __half* __restrict__ Ch, __half* __restrict__ Cl)
{
    extern __shared__ char smem[];
    const uint32_t sQ = smem_u32(smem);

    const int qt  = gridDim.x - 1 - blockIdx.x;   // heavy tiles first
    const int h   = blockIdx.y;
    const int b   = blockIdx.z;
    const int tid = threadIdx.x;
    const int w   = tid >> 5;
    const int l   = tid & 31;
    const int q0  = qt * 64;

    const int lr  = tid >> 1;
    const int lc  = tid & 1;

    const int frow = (l & 7) + ((l >> 3) & 1) * 8;
    const int fch  = l >> 4;

    {
        const __half* qs = Qs + (size_t)(b * SEQ + q0 + lr) * EMBD + h * HDIM;
        #pragma unroll
        for (int i = 0; i < 4; ++i) {
            const int c = lc * 4 + i;
            const uint32_t o = lr * 128 + ((c ^ (lr & 7)) << 4);
            CP_ASYNC16(sQ + o, qs + c * 8);
        }
    }
    auto load_stage = [&](int kt, int buf) {
        const uint32_t sb = sQ + AT + buf * ASTG;
        const __half* ks = Ks + (size_t)(b * SEQ + kt * 64 + lr) * EMBD + h * HDIM;
        const __half* vs = Vt + (size_t)((b * NHEAD + h) * HDIM + lr) * SEQ + kt * 64;
        #pragma unroll
        for (int i = 0; i < 4; ++i) {
            const int c = lc * 4 + i;
            const uint32_t o = lr * 128 + ((c ^ (lr & 7)) << 4);
            CP_ASYNC16(sb + o,      ks + c * 8);
            CP_ASYNC16(sb + AT + o, vs + c * 8);
        }
    };
    load_stage(0, 0);
    CP_COMMIT();

    float o_[8][4];
    #pragma unroll
    for (int nt = 0; nt < 8; ++nt)
        #pragma unroll
        for (int c = 0; c < 4; ++c) o_[nt][c] = 0.f;
    float mA = -1e30f, mB = -1e30f, lA = 0.f, lB = 0.f;

    const int rA = w * 16 + (l >> 2);
    const int cBase = (l & 3) * 2;

    for (int kt = 0; kt <= qt; ++kt) {
        const int buf = kt & 1;
        CP_WAIT0();
        __syncthreads();
        if (kt < qt) { load_stage(kt + 1, buf ^ 1); CP_COMMIT(); }

        const uint32_t sb = sQ + AT + buf * ASTG;

        float s[8][4];
        #pragma unroll
        for (int nt = 0; nt < 8; ++nt)
            #pragma unroll
            for (int c = 0; c < 4; ++c) s[nt][c] = 0.f;

        #pragma unroll
        for (int kk = 0; kk < 4; ++kk) {
            const int cI = kk * 2 + fch;
            uint32_t qf[4], kf[4][4];
            {
                const int qr = w * 16 + frow;
                const uint32_t qa = sQ + qr * 128 + ((cI ^ (qr & 7)) << 4);
                LDSM4(qf, qa);
            }
            #pragma unroll
            for (int p = 0; p < 4; ++p) {
                const int kr = p * 16 + frow;
                const uint32_t ka = sb + kr * 128 + ((cI ^ (kr & 7)) << 4);
                LDSM4(kf[p], ka);
            }
            #pragma unroll
            for (int nt = 0; nt < 8; ++nt) {
                const int p = nt >> 1, o = nt & 1;
                MMA_FP16(s[nt], qf, kf[p][0 + o], kf[p][2 + o]);
            }
        }

        if (kt == qt) {
            #pragma unroll
            for (int nt = 0; nt < 8; ++nt) {
                const int c0 = nt * 8 + cBase;
                if (c0 > rA)         s[nt][0] = -1e30f;
                if (c0 + 1 > rA)     s[nt][1] = -1e30f;
                if (c0 > rA + 8)     s[nt][2] = -1e30f;
                if (c0 + 1 > rA + 8) s[nt][3] = -1e30f;
            }
        }

        float mlA = -1e30f, mlB = -1e30f;
        #pragma unroll
        for (int nt = 0; nt < 8; ++nt) {
            mlA = fmaxf(mlA, fmaxf(s[nt][0], s[nt][1]));
            mlB = fmaxf(mlB, fmaxf(s[nt][2], s[nt][3]));
        }
        mlA = fmaxf(mlA, __shfl_xor_sync(0xffffffffu, mlA, 1));
        mlA = fmaxf(mlA, __shfl_xor_sync(0xffffffffu, mlA, 2));
        mlB = fmaxf(mlB, __shfl_xor_sync(0xffffffffu, mlB, 1));
        mlB = fmaxf(mlB, __shfl_xor_sync(0xffffffffu, mlB, 2));
        const float mAn = fmaxf(mA, mlA);
        const float mBn = fmaxf(mB, mlB);
        const float aAl = exp2f_fast(mA - mAn);
        const float aBl = exp2f_fast(mB - mBn);
        mA = mAn; mB = mBn;

        float sumA = 0.f, sumB = 0.f;
        #pragma unroll
        for (int nt = 0; nt < 8; ++nt) {
            s[nt][0] = exp2f_fast(s[nt][0] - mAn);
            s[nt][1] = exp2f_fast(s[nt][1] - mAn);
            s[nt][2] = exp2f_fast(s[nt][2] - mBn);
            s[nt][3] = exp2f_fast(s[nt][3] - mBn);
            sumA += s[nt][0] + s[nt][1];
            sumB += s[nt][2] + s[nt][3];
        }
        sumA += __shfl_xor_sync(0xffffffffu, sumA, 1);
        sumA += __shfl_xor_sync(0xffffffffu, sumA, 2);
        sumB += __shfl_xor_sync(0xffffffffu, sumB, 1);
        sumB += __shfl_xor_sync(0xffffffffu, sumB, 2);
        lA = lA * aAl + sumA;
        lB = lB * aBl + sumB;

        #pragma unroll
        for (int nt = 0; nt < 8; ++nt) {
            o_[nt][0] *= aAl; o_[nt][1] *= aAl;
            o_[nt][2] *= aBl; o_[nt][3] *= aBl;
        }

        #pragma unroll
        for (int kp = 0; kp < 4; ++kp) {
            uint32_t pf[4];
            pf[0] = packh2(s[2 * kp][0],     s[2 * kp][1]);
            pf[1] = packh2(s[2 * kp][2],     s[2 * kp][3]);
            pf[2] = packh2(s[2 * kp + 1][0], s[2 * kp + 1][1]);
            pf[3] = packh2(s[2 * kp + 1][2], s[2 * kp + 1][3]);

            const int cI = kp * 2 + fch;
            uint32_t vf[4][4];
            #pragma unroll
            for (int p = 0; p < 4; ++p) {
                const int vr = p * 16 + frow;
                const uint32_t va = sb + AT + vr * 128 + ((cI ^ (vr & 7)) << 4);
                LDSM4(vf[p], va);
            }
            #pragma unroll
            for (int nt = 0; nt < 8; ++nt) {
                const int p = nt >> 1, o = nt & 1;
                MMA_FP16(o_[nt], pf, vf[p][0 + o], vf[p][2 + o]);
            }
        }
    }

    const float iA = 1.0f / lA, iB = 1.0f / lB;
    const size_t row0 = (size_t)(b * SEQ + q0 + rA);
    #pragma unroll
    for (int nt = 0; nt < 8; ++nt) {
        const int d = h * HDIM + nt * 8 + cBase;
        uint32_t h0, l0, h1, l1;
        split2h(o_[nt][0] * iA, o_[nt][1] * iA, h0, l0);
        split2h(o_[nt][2] * iB, o_[nt][3] * iB, h1, l1);
        *(uint32_t*)(Ch + row0 * EMBD + d)       = h0;
        *(uint32_t*)(Cl + row0 * EMBD + d)       = l0;
        *(uint32_t*)(Ch + (row0 + 8) * EMBD + d) = h1;
        *(uint32_t*)(Cl + (row0 + 8) * EMBD + d) = l1;
    }
}

// ---------------------------------------------------------------------------
// prep kernels
// ---------------------------------------------------------------------------
__global__ __launch_bounds__(256) void split_pair_h(
    const float4* __restrict__ src, uint2* __restrict__ h, uint2* __restrict__ l, int n4)
{
    const int i = blockIdx.x * 256 + threadIdx.x;
    if (i >= n4) return;
    const float4 v = src[i];
    uint32_t h0, l0, h1, l1;
    split2h(v.x, v.y, h0, l0);
    split2h(v.z, v.w, h1, l1);
    h[i] = make_uint2(h0, h1);
    l[i] = make_uint2(l0, l1);
}

__global__ void transpose_half(const float* __restrict__ W,
                               __half* __restrict__ T, int K, int N)
{
    __shared__ float t[32][33];
    const int k0 = blockIdx.y * 32, n0 = blockIdx.x * 32;
    const int x = threadIdx.x, y = threadIdx.y;
    #pragma unroll
    for (int i = 0; i < 32; i += 8)
        t[y + i][x] = W[(size_t)(k0 + y + i) * N + n0 + x];
    __syncthreads();
    #pragma unroll
    for (int i = 0; i < 32; i += 8)
        T[(size_t)(n0 + y + i) * K + k0 + x] = __float2half(t[x][y + i]);
}

// V fp16 [tok][h*64+d] -> V^T fp16 [b,h,d][t]
__global__ void vt_tr(const __half* __restrict__ Vh, __half* __restrict__ T)
{
    __shared__ __half t[32][34];
    const int t0 = blockIdx.x * 32;
    const int d0 = blockIdx.y * 32;
    const int bh = blockIdx.z;
    const int b  = bh >> 4, h = bh & 15;
    const int x = threadIdx.x, y = threadIdx.y;
    #pragma unroll
    for (int i = 0; i < 32; i += 8)
        t[y + i][x] = Vh[(size_t)(b * SEQ + t0 + y + i) * EMBD + h * HDIM + d0 + x];
    __syncthreads();
    #pragma unroll
    for (int i = 0; i < 32; i += 8)
        T[(size_t)(bh * HDIM + d0 + y + i) * SEQ + t0 + x] = t[x][y + i];
}

// ---------------------------------------------------------------------------
extern "C" void kernel_launch(void* const* d_in, const int* in_sizes, int n_in,
                              void* d_out, int out_size)
{
    const float* x     = (const float*)d_in[0];
    const float* w_qkv = (const float*)d_in[1];
    const float* b_qkv = (const float*)d_in[2];
    const float* w_out = (const float*)d_in[3];
    const float* b_out = (const float*)d_in[4];
    float* out = (float*)d_out;

    __half *xh, *xl, *ch, *cl, *wq, *wo, *qs, *ks, *vh, *vt;
    cudaGetSymbolAddress((void**)&xh, g_xh);
    cudaGetSymbolAddress((void**)&xl, g_xl);
    cudaGetSymbolAddress((void**)&ch, g_ch);
    cudaGetSymbolAddress((void**)&cl, g_cl);
    cudaGetSymbolAddress((void**)&wq, g_wq);
    cudaGetSymbolAddress((void**)&wo, g_wo);
    cudaGetSymbolAddress((void**)&qs, g_qs);
    cudaGetSymbolAddress((void**)&ks, g_ks);
    cudaGetSymbolAddress((void**)&vh, g_vh);
    cudaGetSymbolAddress((void**)&vt, g_vt);

    cudaFuncSetAttribute(gemm_mma, cudaFuncAttributeMaxDynamicSharedMemorySize, GSMEM);
    cudaFuncSetAttribute(attn_mma, cudaFuncAttributeMaxDynamicSharedMemorySize, ASMEM);

    const int n4 = TOK * EMBD / 4;

    split_pair_h<<<n4 / 256, 256>>>((const float4*)x, (uint2*)xh, (uint2*)xl, n4);
    transpose_half<<<dim3(3 * EMBD / 32, EMBD / 32), dim3(32, 8)>>>(w_qkv, wq, EMBD, 3 * EMBD);
    transpose_half<<<dim3(EMBD / 32, EMBD / 32), dim3(32, 8)>>>(w_out, wo, EMBD, EMBD);

    // 1) fused QKV: q*QSC -> g_qs, k -> g_ks, v -> g_vh  (fp16 epilogue)
    gemm_mma<<<dim3(3 * EMBD / 128, TOK / 128), 256, GSMEM>>>(
        xh, xl, wq, b_qkv, nullptr, qs, ks, vh, 3 * EMBD, 1);

    // 2) transpose V (fp16 -> fp16)
    vt_tr<<<dim3(SEQ / 32, HDIM / 32, 4 * NHEAD), dim3(32, 8)>>>(vh, vt);

    // 3) causal flash attention (single-pass fp16 HMMA)
    attn_mma<<<dim3(SEQ / 64, NHEAD, 4), 128, ASMEM>>>(qs, ks, vt, ch, cl);

    // 4) out = ctx @ w_out + b_out  (fp32 epilogue)
    gemm_mma<<<dim3(EMBD / 128, TOK / 128), 256, GSMEM>>>(
        ch, cl, wo, b_out, out, nullptr, nullptr, nullptr, EMBD, 0);
}

// round 17
// speedup vs baseline: 2.3861x; 1.3648x over previous
#include <cuda_runtime.h>
#include <cuda_fp16.h>
#include <cstdint>
#include <math.h>

#define TOK   8192
#define EMBD  1024
#define SEQ   2048
#define NHEAD 16
#define HDIM  64

// ---------------- scratch (allocation-free rule: device globals) ----------
__device__ __half g_xh[(size_t)TOK * EMBD];           // x fp16
__device__ __half g_ch[(size_t)TOK * EMBD];           // ctx fp16
__device__ __half g_wq[(size_t)3 * EMBD * EMBD];      // w_qkv^T fp16 [N][K]
__device__ __half g_wo[(size_t)EMBD * EMBD];          // w_out^T fp16 [N][K]
// attention operands (fp16, written by fused QKV epilogue)
__device__ __half g_qs[(size_t)TOK * EMBD];           // scaled Q [tok][h*64+d]
__device__ __half g_ks[(size_t)TOK * EMBD];           // K        [tok][h*64+d]
__device__ __half g_vh[(size_t)TOK * EMBD];           // V        [tok][h*64+d]
__device__ __half g_vt[(size_t)TOK * EMBD];           // V^T      [b,h,d][t]

// ---------------- helpers ---------------------------------------------
__device__ __forceinline__ uint32_t smem_u32(const void* p) {
    uint32_t a;
    asm("{ .reg .u64 t; cvta.to.shared.u64 t, %1; cvt.u32.u64 %0, t; }" : "=r"(a) : "l"(p));
    return a;
}

#define LDSM4(r, a) \
    asm volatile("ldmatrix.sync.aligned.m8n8.x4.shared.b16 {%0,%1,%2,%3}, [%4];" \
        : "=r"((r)[0]), "=r"((r)[1]), "=r"((r)[2]), "=r"((r)[3]) : "r"(a))

#define MMA_FP16(c, a, b0, b1) \
    asm volatile("mma.sync.aligned.m16n8k16.row.col.f32.f16.f16.f32 " \
        "{%0,%1,%2,%3},{%4,%5,%6,%7},{%8,%9},{%0,%1,%2,%3};" \
        : "+f"((c)[0]), "+f"((c)[1]), "+f"((c)[2]), "+f"((c)[3]) \
        : "r"((a)[0]), "r"((a)[1]), "r"((a)[2]), "r"((a)[3]), "r"(b0), "r"(b1))

#define CP_ASYNC16(so, gp) \
    asm volatile("cp.async.cg.shared.global [%0], [%1], 16;" :: "r"(so), "l"(gp) : "memory")
#define CP_COMMIT() asm volatile("cp.async.commit_group;" ::: "memory")
#define CP_WAIT0()  asm volatile("cp.async.wait_group 0;" ::: "memory")
#define CP_WAIT1()  asm volatile("cp.async.wait_group 1;" ::: "memory")

// fast exp2 on fma pipe (arg <= 0, clamped), rel err ~2e-5
__device__ __forceinline__ float exp2f_fast(float t) {
    t = fmaxf(t, -100.0f);
    float fi = floorf(t);
    float f  = t - fi;
    float p  = 1.33335581e-3f;
    p = fmaf(p, f, 9.61812910e-3f);
    p = fmaf(p, f, 5.55041087e-2f);
    p = fmaf(p, f, 2.40226507e-1f);
    p = fmaf(p, f, 6.93147182e-1f);
    p = fmaf(p, f, 1.0f);
    return __int_as_float(((int)fi + 127) << 23) * p;
}

__device__ __forceinline__ uint32_t packh2(float x, float y) {
    __half2 t = __floats2half2_rn(x, y);
    return *reinterpret_cast<uint32_t*>(&t);
}

// ---------------------------------------------------------------------------
// mma.sync fp16 single-term GEMM: C = A[M,1024] @ B[N,1024]^T + bias.
// Block 128x128, warp 64x32, K-slab 32, 3-stage cp.async ring, 2 blocks/SM.
// mode 0: C fp32 + bias. mode 1 (fused qkv): per-region fp16 stores
//         (q*QSC -> Q, k -> Kd, v -> V), region = n0/1024, uniform per block.
// ---------------------------------------------------------------------------
#define LDB    80
#define TILEB  (128 * LDB)          // 10240 B
#define GSTAGE (2 * TILEB)          // A | B = 20480 B
#define GSMEM  (3 * GSTAGE)         // 61440 B

__global__ __launch_bounds__(256) void gemm_mma(
    const __half* __restrict__ A, const __half* __restrict__ B,
    const float* __restrict__ bias,
    float* __restrict__ C, __half* __restrict__ Q, __half* __restrict__ Kd,
    __half* __restrict__ V, int N, int mode)
{
    extern __shared__ char smem[];
    const uint32_t sbase = smem_u32(smem);
    const int tid = threadIdx.x;
    const int wid = tid >> 5;
    const int l   = tid & 31;
    const int m0  = blockIdx.y * 128;
    const int n0  = blockIdx.x * 128;
    const int wm  = (wid >> 2) * 64;
    const int wn  = (wid & 3) * 32;

    const __half* srcs[2] = { A + (size_t)m0 * 1024, B + (size_t)n0 * 1024 };

    const int frow = (l & 7) + ((l >> 3) & 1) * 8;
    const int fkb  = (l >> 4) * 16;

    float acc[4][4][4];
    #pragma unroll
    for (int a = 0; a < 4; ++a)
        #pragma unroll
        for (int b = 0; b < 4; ++b)
            #pragma unroll
            for (int c = 0; c < 4; ++c) acc[a][b][c] = 0.f;

    auto load_stage = [&](int ks) {
        const uint32_t sb = sbase + (ks % 3) * GSTAGE;
        const int kc = ks * 32;
        #pragma unroll
        for (int t = 0; t < 2; ++t) {
            #pragma unroll
            for (int j = 0; j < 2; ++j) {
                const int chunk = j * 256 + tid;        // 0..511
                const int row = chunk >> 2, seg = chunk & 3;
                const uint32_t so = sb + t * TILEB + row * LDB + seg * 16;
                CP_ASYNC16(so, srcs[t] + (size_t)row * 1024 + kc + seg * 8);
            }
        }
    };

    load_stage(0); CP_COMMIT();
    load_stage(1); CP_COMMIT();

    for (int ks = 0; ks < 32; ++ks) {
        if (ks + 2 < 32) CP_WAIT1(); else CP_WAIT0();
        __syncthreads();
        if (ks + 2 < 32) { load_stage(ks + 2); CP_COMMIT(); }

        const uint32_t sb = sbase + (ks % 3) * GSTAGE;
        #pragma unroll
        for (int kk = 0; kk < 2; ++kk) {
            const uint32_t kbo = kk * 32 + fkb;
            uint32_t ah[4][4], bh[2][4];
            #pragma unroll
            for (int mt = 0; mt < 4; ++mt) {
                LDSM4(ah[mt], sb + (wm + mt * 16 + frow) * LDB + kbo);
            }
            #pragma unroll
            for (int p = 0; p < 2; ++p) {
                LDSM4(bh[p], sb + TILEB + (wn + p * 16 + frow) * LDB + kbo);
            }
            #pragma unroll
            for (int mt = 0; mt < 4; ++mt)
                #pragma unroll
                for (int nt = 0; nt < 4; ++nt) {
                    const int p = nt >> 1, o = nt & 1;
                    MMA_FP16(acc[mt][nt], ah[mt], bh[p][0 + o], bh[p][2 + o]);
                }
        }
    }

    __syncthreads();
    const int er = l >> 2, ec = (l & 3) * 2;

    if (mode == 0) {
        #pragma unroll
        for (int mt = 0; mt < 4; ++mt) {
            #pragma unroll
            for (int nt = 0; nt < 4; ++nt) {
                const int m = m0 + wm + mt * 16 + er;
                const int n = n0 + wn + nt * 8 + ec;
                const float b0 = __ldg(bias + n), b1 = __ldg(bias + n + 1);
                float2 v0 = { acc[mt][nt][0] + b0, acc[mt][nt][1] + b1 };
                float2 v1 = { acc[mt][nt][2] + b0, acc[mt][nt][3] + b1 };
                *(float2*)(C + (size_t)m * N + n)       = v0;
                *(float2*)(C + (size_t)(m + 8) * N + n) = v1;
            }
        }
    } else {
        const int region = n0 >> 10;                 // 0=q 1=k 2=v
        const float QSC = 0.1803368801111244f;       // 0.125*log2(e)
        const float sc = (region == 0) ? QSC : 1.0f;
        __half* dst = (region == 0) ? Q : (region == 1 ? Kd : V);
        const int nb = n0 & 1023;
        #pragma unroll
        for (int mt = 0; mt < 4; ++mt) {
            #pragma unroll
            for (int nt = 0; nt < 4; ++nt) {
                const int m = m0 + wm + mt * 16 + er;
                const int n = n0 + wn + nt * 8 + ec;
                const int nl = nb + wn + nt * 8 + ec;
                const float b0 = __ldg(bias + n), b1 = __ldg(bias + n + 1);
                const uint32_t h0 = packh2((acc[mt][nt][0] + b0) * sc,
                                           (acc[mt][nt][1] + b1) * sc);
                const uint32_t h1 = packh2((acc[mt][nt][2] + b0) * sc,
                                           (acc[mt][nt][3] + b1) * sc);
                *(uint32_t*)(dst + (size_t)m * 1024 + nl)       = h0;
                *(uint32_t*)(dst + (size_t)(m + 8) * 1024 + nl) = h1;
            }
        }
    }
}

// ---------------------------------------------------------------------------
// HMMA flash attention, single-pass fp16 (fp32 accumulate) — proven config.
// Output: single fp16 ctx (feeds single-term out-proj GEMM).
// ---------------------------------------------------------------------------
#define AT    8192                  // one 64x64 fp16 tile
#define ASTG  (2 * AT)              // K,V per stage
#define ASMEM (AT + 2 * ASTG)       // 40960 B

__global__ __launch_bounds__(128) void attn_mma(
    const __half* __restrict__ Qs, const __half* __restrict__ Ks,
    const __half* __restrict__ Vt, __half* __restrict__ Ch)
{
    extern __shared__ char smem[];
    const uint32_t sQ = smem_u32(smem);

    const int qt  = gridDim.x - 1 - blockIdx.x;   // heavy tiles first
    const int h   = blockIdx.y;
    const int b   = blockIdx.z;
    const int tid = threadIdx.x;
    const int w   = tid >> 5;
    const int l   = tid & 31;
    const int q0  = qt * 64;

    const int lr  = tid >> 1;
    const int lc  = tid & 1;

    const int frow = (l & 7) + ((l >> 3) & 1) * 8;
    const int fch  = l >> 4;

    {
        const __half* qs = Qs + (size_t)(b * SEQ + q0 + lr) * EMBD + h * HDIM;
        #pragma unroll
        for (int i = 0; i < 4; ++i) {
            const int c = lc * 4 + i;
            const uint32_t o = lr * 128 + ((c ^ (lr & 7)) << 4);
            CP_ASYNC16(sQ + o, qs + c * 8);
        }
    }
    auto load_stage = [&](int kt, int buf) {
        const uint32_t sb = sQ + AT + buf * ASTG;
        const __half* ks = Ks + (size_t)(b * SEQ + kt * 64 + lr) * EMBD + h * HDIM;
        const __half* vs = Vt + (size_t)((b * NHEAD + h) * HDIM + lr) * SEQ + kt * 64;
        #pragma unroll
        for (int i = 0; i < 4; ++i) {
            const int c = lc * 4 + i;
            const uint32_t o = lr * 128 + ((c ^ (lr & 7)) << 4);
            CP_ASYNC16(sb + o,      ks + c * 8);
            CP_ASYNC16(sb + AT + o, vs + c * 8);
        }
    };
    load_stage(0, 0);
    CP_COMMIT();

    float o_[8][4];
    #pragma unroll
    for (int nt = 0; nt < 8; ++nt)
        #pragma unroll
        for (int c = 0; c < 4; ++c) o_[nt][c] = 0.f;
    float mA = -1e30f, mB = -1e30f, lA = 0.f, lB = 0.f;

    const int rA = w * 16 + (l >> 2);
    const int cBase = (l & 3) * 2;

    for (int kt = 0; kt <= qt; ++kt) {
        const int buf = kt & 1;
        CP_WAIT0();
        __syncthreads();
        if (kt < qt) { load_stage(kt + 1, buf ^ 1); CP_COMMIT(); }

        const uint32_t sb = sQ + AT + buf * ASTG;

        float s[8][4];
        #pragma unroll
        for (int nt = 0; nt < 8; ++nt)
            #pragma unroll
            for (int c = 0; c < 4; ++c) s[nt][c] = 0.f;

        #pragma unroll
        for (int kk = 0; kk < 4; ++kk) {
            const int cI = kk * 2 + fch;
            uint32_t qf[4], kf[4][4];
            {
                const int qr = w * 16 + frow;
                const uint32_t qa = sQ + qr * 128 + ((cI ^ (qr & 7)) << 4);
                LDSM4(qf, qa);
            }
            #pragma unroll
            for (int p = 0; p < 4; ++p) {
                const int kr = p * 16 + frow;
                const uint32_t ka = sb + kr * 128 + ((cI ^ (kr & 7)) << 4);
                LDSM4(kf[p], ka);
            }
            #pragma unroll
            for (int nt = 0; nt < 8; ++nt) {
                const int p = nt >> 1, o = nt & 1;
                MMA_FP16(s[nt], qf, kf[p][0 + o], kf[p][2 + o]);
            }
        }

        if (kt == qt) {
            #pragma unroll
            for (int nt = 0; nt < 8; ++nt) {
                const int c0 = nt * 8 + cBase;
                if (c0 > rA)         s[nt][0] = -1e30f;
                if (c0 + 1 > rA)     s[nt][1] = -1e30f;
                if (c0 > rA + 8)     s[nt][2] = -1e30f;
                if (c0 + 1 > rA + 8) s[nt][3] = -1e30f;
            }
        }

        float mlA = -1e30f, mlB = -1e30f;
        #pragma unroll
        for (int nt = 0; nt < 8; ++nt) {
            mlA = fmaxf(mlA, fmaxf(s[nt][0], s[nt][1]));
            mlB = fmaxf(mlB, fmaxf(s[nt][2], s[nt][3]));
        }
        mlA = fmaxf(mlA, __shfl_xor_sync(0xffffffffu, mlA, 1));
        mlA = fmaxf(mlA, __shfl_xor_sync(0xffffffffu, mlA, 2));
        mlB = fmaxf(mlB, __shfl_xor_sync(0xffffffffu, mlB, 1));
        mlB = fmaxf(mlB, __shfl_xor_sync(0xffffffffu, mlB, 2));
        const float mAn = fmaxf(mA, mlA);
        const float mBn = fmaxf(mB, mlB);
        const float aAl = exp2f_fast(mA - mAn);
        const float aBl = exp2f_fast(mB - mBn);
        mA = mAn; mB = mBn;

        float sumA = 0.f, sumB = 0.f;
        #pragma unroll
        for (int nt = 0; nt < 8; ++nt) {
            s[nt][0] = exp2f_fast(s[nt][0] - mAn);
            s[nt][1] = exp2f_fast(s[nt][1] - mAn);
            s[nt][2] = exp2f_fast(s[nt][2] - mBn);
            s[nt][3] = exp2f_fast(s[nt][3] - mBn);
            sumA += s[nt][0] + s[nt][1];
            sumB += s[nt][2] + s[nt][3];
        }
        sumA += __shfl_xor_sync(0xffffffffu, sumA, 1);
        sumA += __shfl_xor_sync(0xffffffffu, sumA, 2);
        sumB += __shfl_xor_sync(0xffffffffu, sumB, 1);
        sumB += __shfl_xor_sync(0xffffffffu, sumB, 2);
        lA = lA * aAl + sumA;
        lB = lB * aBl + sumB;

        #pragma unroll
        for (int nt = 0; nt < 8; ++nt) {
            o_[nt][0] *= aAl; o_[nt][1] *= aAl;
            o_[nt][2] *= aBl; o_[nt][3] *= aBl;
        }

        #pragma unroll
        for (int kp = 0; kp < 4; ++kp) {
            uint32_t pf[4];
            pf[0] = packh2(s[2 * kp][0],     s[2 * kp][1]);
            pf[1] = packh2(s[2 * kp][2],     s[2 * kp][3]);
            pf[2] = packh2(s[2 * kp + 1][0], s[2 * kp + 1][1]);
            pf[3] = packh2(s[2 * kp + 1][2], s[2 * kp + 1][3]);

            const int cI = kp * 2 + fch;
            uint32_t vf[4][4];
            #pragma unroll
            for (int p = 0; p < 4; ++p) {
                const int vr = p * 16 + frow;
                const uint32_t va = sb + AT + vr * 128 + ((cI ^ (vr & 7)) << 4);
                LDSM4(vf[p], va);
            }
            #pragma unroll
            for (int nt = 0; nt < 8; ++nt) {
                const int p = nt >> 1, o = nt & 1;
                MMA_FP16(o_[nt], pf, vf[p][0 + o], vf[p][2 + o]);
            }
        }
    }

    const float iA = 1.0f / lA, iB = 1.0f / lB;
    const size_t row0 = (size_t)(b * SEQ + q0 + rA);
    #pragma unroll
    for (int nt = 0; nt < 8; ++nt) {
        const int d = h * HDIM + nt * 8 + cBase;
        *(uint32_t*)(Ch + row0 * EMBD + d)       = packh2(o_[nt][0] * iA, o_[nt][1] * iA);
        *(uint32_t*)(Ch + (row0 + 8) * EMBD + d) = packh2(o_[nt][2] * iB, o_[nt][3] * iB);
    }
}

// ---------------------------------------------------------------------------
// prep kernels
// ---------------------------------------------------------------------------
__global__ __launch_bounds__(256) void to_half(
    const float4* __restrict__ src, uint2* __restrict__ dst, int n4)
{
    const int i = blockIdx.x * 256 + threadIdx.x;
    if (i >= n4) return;
    const float4 v = src[i];
    dst[i] = make_uint2(packh2(v.x, v.y), packh2(v.z, v.w));
}

__global__ void transpose_half(const float* __restrict__ W,
                               __half* __restrict__ T, int K, int N)
{
    __shared__ float t[32][33];
    const int k0 = blockIdx.y * 32, n0 = blockIdx.x * 32;
    const int x = threadIdx.x, y = threadIdx.y;
    #pragma unroll
    for (int i = 0; i < 32; i += 8)
        t[y + i][x] = W[(size_t)(k0 + y + i) * N + n0 + x];
    __syncthreads();
    #pragma unroll
    for (int i = 0; i < 32; i += 8)
        T[(size_t)(n0 + y + i) * K + k0 + x] = __float2half(t[x][y + i]);
}

// V fp16 [tok][h*64+d] -> V^T fp16 [b,h,d][t]
__global__ void vt_tr(const __half* __restrict__ Vh, __half* __restrict__ T)
{
    __shared__ __half t[32][34];
    const int t0 = blockIdx.x * 32;
    const int d0 = blockIdx.y * 32;
    const int bh = blockIdx.z;
    const int b  = bh >> 4, h = bh & 15;
    const int x = threadIdx.x, y = threadIdx.y;
    #pragma unroll
    for (int i = 0; i < 32; i += 8)
        t[y + i][x] = Vh[(size_t)(b * SEQ + t0 + y + i) * EMBD + h * HDIM + d0 + x];
    __syncthreads();
    #pragma unroll
    for (int i = 0; i < 32; i += 8)
        T[(size_t)(bh * HDIM + d0 + y + i) * SEQ + t0 + x] = t[x][y + i];
}

// ---------------------------------------------------------------------------
extern "C" void kernel_launch(void* const* d_in, const int* in_sizes, int n_in,
                              void* d_out, int out_size)
{
    const float* x     = (const float*)d_in[0];
    const float* w_qkv = (const float*)d_in[1];
    const float* b_qkv = (const float*)d_in[2];
    const float* w_out = (const float*)d_in[3];
    const float* b_out = (const float*)d_in[4];
    float* out = (float*)d_out;

    __half *xh, *ch, *wq, *wo, *qs, *ks, *vh, *vt;
    cudaGetSymbolAddress((void**)&xh, g_xh);
    cudaGetSymbolAddress((void**)&ch, g_ch);
    cudaGetSymbolAddress((void**)&wq, g_wq);
    cudaGetSymbolAddress((void**)&wo, g_wo);
    cudaGetSymbolAddress((void**)&qs, g_qs);
    cudaGetSymbolAddress((void**)&ks, g_ks);
    cudaGetSymbolAddress((void**)&vh, g_vh);
    cudaGetSymbolAddress((void**)&vt, g_vt);

    cudaFuncSetAttribute(gemm_mma, cudaFuncAttributeMaxDynamicSharedMemorySize, GSMEM);
    cudaFuncSetAttribute(attn_mma, cudaFuncAttributeMaxDynamicSharedMemorySize, ASMEM);

    const int n4 = TOK * EMBD / 4;

    to_half<<<n4 / 256, 256>>>((const float4*)x, (uint2*)xh, n4);
    transpose_half<<<dim3(3 * EMBD / 32, EMBD / 32), dim3(32, 8)>>>(w_qkv, wq, EMBD, 3 * EMBD);
    transpose_half<<<dim3(EMBD / 32, EMBD / 32), dim3(32, 8)>>>(w_out, wo, EMBD, EMBD);

    // 1) fused QKV: q*QSC -> g_qs, k -> g_ks, v -> g_vh  (fp16 epilogue)
    gemm_mma<<<dim3(3 * EMBD / 128, TOK / 128), 256, GSMEM>>>(
        xh, wq, b_qkv, nullptr, qs, ks, vh, 3 * EMBD, 1);

    // 2) transpose V (fp16 -> fp16)
    vt_tr<<<dim3(SEQ / 32, HDIM / 32, 4 * NHEAD), dim3(32, 8)>>>(vh, vt);

    // 3) causal flash attention (single-pass fp16 HMMA)
    attn_mma<<<dim3(SEQ / 64, NHEAD, 4), 128, ASMEM>>>(qs, ks, vt, ch);

    // 4) out = ctx @ w_out + b_out  (fp32 epilogue)
    gemm_mma<<<dim3(EMBD / 128, TOK / 128), 256, GSMEM>>>(
        ch, wo, b_out, out, nullptr, nullptr, nullptr, EMBD, 0);
}